// round 12
// baseline (speedup 1.0000x reference)
#include <cuda_runtime.h>
#include <cuda_fp16.h>
#include <cstdint>
#include <cstddef>

#define BB 8
#define NN 4096
#define DD 1024
#define KSLOT 128
#define MTOT (BB * NN)        // 32768
#define NCHUNK 32             // NN / 128
#define NSPLIT 8              // split-K for weight prep

// ---------------- scratch ----------------
__device__ float g_logits[(size_t)MTOT * KSLOT];// 16 MiB (raw logits)
__device__ float g_pm[BB * NCHUNK * KSLOT];
__device__ float g_ps[BB * NCHUNK * KSLOT];
__device__ float g_Pa[(size_t)NSPLIT * KSLOT * DD];
__device__ float g_Pb[(size_t)NSPLIT * DD * KSLOT];
__device__ float g_Wag[(size_t)KSLOT * DD];
__device__ float g_wsum[KSLOT];
__device__ float g_cb[KSLOT];
__device__ __half g_WbH[(size_t)DD * KSLOT];    // (w_out @ w1) rounded to fp16, [e,k]

#define NEG_INF __int_as_float(0xff800000)

// ---------------- fp16 split helpers ----------------
__device__ __forceinline__ uint32_t pack_f16(float2 v) {
    __half2 h = __floats2half2_rn(v.x, v.y);
    return *reinterpret_cast<uint32_t*>(&h);
}

__device__ __forceinline__ void split_f16(float2 v, uint32_t& hi, uint32_t& lo) {
    __half2 h = __floats2half2_rn(v.x, v.y);
    hi = *reinterpret_cast<uint32_t*>(&h);
    const float2 hf = __half22float2(h);
    __half2 l = __floats2half2_rn(v.x - hf.x, v.y - hf.y);
    lo = *reinterpret_cast<uint32_t*>(&l);
}

// m16n8k16 fp16 MMA, fp32 accumulate
__device__ __forceinline__ void mma_f16(float* c,
                                        uint32_t a0, uint32_t a1, uint32_t a2, uint32_t a3,
                                        uint32_t b0, uint32_t b1) {
    asm volatile(
        "mma.sync.aligned.m16n8k16.row.col.f32.f16.f16.f32 "
        "{%0,%1,%2,%3}, {%4,%5,%6,%7}, {%8,%9}, {%0,%1,%2,%3};"
        : "+f"(c[0]), "+f"(c[1]), "+f"(c[2]), "+f"(c[3])
        : "r"(a0), "r"(a1), "r"(a2), "r"(a3), "r"(b0), "r"(b1));
}

__device__ __forceinline__ uint32_t smem_u32(const void* p) {
    uint32_t addr;
    asm("{ .reg .u64 tmp; cvta.to.shared.u64 tmp, %1; cvt.u32.u64 %0, tmp; }"
        : "=r"(addr) : "l"(p));
    return addr;
}

#define CP_ASYNC16(dst, src) \
    asm volatile("cp.async.cg.shared.global [%0], [%1], 16;\n" ::"r"(dst), "l"(src))
#define CP_COMMIT() asm volatile("cp.async.commit_group;\n")
#define CP_WAIT(N_) asm volatile("cp.async.wait_group %0;\n" ::"n"(N_))

// ================= fused h3 GEMM + softmax(pass2+norm) + LN + residual + relu =================
// block = 32 rows of logits (BM=32), full N=1024 columns, K=128. 256 threads (R10 shape).
#define H3S 1036
#define FH_A_OFF   132608               // 32*1036*4
#define FH_A_STR   132
#define FH_B_OFF   149504               // FH_A_OFF + 32*132*4
#define FH_B_STR   136
#define FH_B_SZ    34816                // 128*136*2
#define FH_PART_OFF 219136              // FH_B_OFF + 2*FH_B_SZ
#define FH_STAT_OFF 220160              // + 256 floats of partials
#define FH_MS_OFF   220416              // + mean[32]+rstd[32]
#define FH_SMEM     221440              // + M[128] + S[128]

__global__ void __launch_bounds__(256, 1)
h3_final_fused(const float* __restrict__ A, const __half* __restrict__ WbH,
               const float* __restrict__ xres, const float* __restrict__ gg,
               const float* __restrict__ bb, float* __restrict__ out) {
    extern __shared__ char sm[];
    const uint32_t sbase = smem_u32(sm);
    float* h3s = reinterpret_cast<float*>(sm);
    float* As  = reinterpret_cast<float*>(sm + FH_A_OFF);
    float* part = reinterpret_cast<float*>(sm + FH_PART_OFF);
    float* stat = reinterpret_cast<float*>(sm + FH_STAT_OFF);
    float* sM   = reinterpret_cast<float*>(sm + FH_MS_OFF);        // [128]
    float* sS   = reinterpret_cast<float*>(sm + FH_MS_OFF + 512);  // [128]

    const int tid  = threadIdx.x;
    const int warp = tid >> 5;
    const int lane = tid & 31;
    const int wm   = warp & 1;
    const int wn   = warp >> 1;
    const int g    = lane >> 2;
    const int t    = lane & 3;
    const int brow = blockIdx.x * 32;
    const int b    = brow >> 12;

    part[tid] = 0.f;

    // issue A stage (32 x 128 fp32 raw logits) + B tile 0
#pragma unroll
    for (int i = 0; i < 4; ++i) {
        const int linear = tid + i * 256;
        const int row = linear >> 5;
        const int c   = linear & 31;
        CP_ASYNC16(sbase + FH_A_OFF + row * (FH_A_STR * 4) + c * 16,
                   (const char*)A + (size_t)(brow + row) * KSLOT * 4 + c * 16);
    }
#pragma unroll
    for (int i = 0; i < 8; ++i) {
        const int linear = tid + i * 256;
        const int e = linear >> 4;
        const int c = linear & 15;
        CP_ASYNC16(sbase + FH_B_OFF + e * (FH_B_STR * 2) + c * 16,
                   (const char*)WbH + (size_t)e * KSLOT * 2 + c * 16);
    }
    CP_COMMIT();
#pragma unroll
    for (int i = 0; i < 8; ++i) {
        const int linear = tid + i * 256;
        const int e = linear >> 4;
        const int c = linear & 15;
        CP_ASYNC16(sbase + FH_B_OFF + FH_B_SZ + e * (FH_B_STR * 2) + c * 16,
                   (const char*)WbH + (size_t)(128 + e) * KSLOT * 2 + c * 16);
    }
    CP_COMMIT();

    // softmax pass2 (fused): combine chunk partials for this batch -> sM/sS.
    // Independent of the cp.async traffic above; overlaps the loads.
    if (tid < KSLOT) {
        const int k = tid;
        float M = NEG_INF;
#pragma unroll 4
        for (int c = 0; c < NCHUNK; ++c)
            M = fmaxf(M, g_pm[(b * NCHUNK + c) * KSLOT + k]);
        float S = 0.f;
#pragma unroll 4
        for (int c = 0; c < NCHUNK; ++c)
            S += g_ps[(b * NCHUNK + c) * KSLOT + k] *
                 __expf(g_pm[(b * NCHUNK + c) * KSLOT + k] - M);
        sM[k] = M;
        sS[k] = S;
    }

    uint32_t ah[8][4], al[8][4];
    float acc[4][4];
#pragma unroll
    for (int nf = 0; nf < 4; ++nf)
#pragma unroll
        for (int q = 0; q < 4; ++q) acc[nf][q] = 0.f;
    float s0 = 0.f, q0 = 0.f, s1 = 0.f, q1 = 0.f;

    for (int nt = 0; nt < 8; ++nt) {
        if (nt < 6) { CP_WAIT(1); } else { CP_WAIT(0); }
        __syncthreads();

        if (nt == 0) {
            // softmax-normalize A tile in place: p = exp(l - M)/S, then L1 over k
            {
                const int row = tid >> 3;
                const int c0 = (tid & 7) * 16;
                float* ar = &As[row * FH_A_STR + c0];
                float pv[16];
                float tot = 0.f;
#pragma unroll
                for (int j = 0; j < 16; ++j) {
                    const int k = c0 + j;
                    pv[j] = __expf(ar[j] - sM[k]) / sS[k];
                    tot += pv[j];
                }
                tot += __shfl_xor_sync(0xffffffffu, tot, 1);
                tot += __shfl_xor_sync(0xffffffffu, tot, 2);
                tot += __shfl_xor_sync(0xffffffffu, tot, 4);
                const float inv = 1.f / (1e-9f + tot);
#pragma unroll
                for (int j = 0; j < 16; ++j) ar[j] = pv[j] * inv;
            }
            __syncthreads();

            // convert this warp's A fragments once (rows wm*16+g, +8; all K)
            const int r0 = wm * 16 + g;
#pragma unroll
            for (int kk = 0; kk < 8; ++kk) {
                const int kb = kk * 16 + 2 * t;
                const float2 v0 = *reinterpret_cast<const float2*>(&As[r0 * FH_A_STR + kb]);
                const float2 v1 = *reinterpret_cast<const float2*>(&As[(r0 + 8) * FH_A_STR + kb]);
                const float2 v2 = *reinterpret_cast<const float2*>(&As[r0 * FH_A_STR + kb + 8]);
                const float2 v3 = *reinterpret_cast<const float2*>(&As[(r0 + 8) * FH_A_STR + kb + 8]);
                split_f16(v0, ah[kk][0], al[kk][0]);
                split_f16(v1, ah[kk][1], al[kk][1]);
                split_f16(v2, ah[kk][2], al[kk][2]);
                split_f16(v3, ah[kk][3], al[kk][3]);
            }
        }

        const char* bB = sm + FH_B_OFF + (nt & 1) * FH_B_SZ;
#pragma unroll
        for (int kk = 0; kk < 8; ++kk) {
            uint32_t b0[4], b1[4];
#pragma unroll
            for (int nf = 0; nf < 4; ++nf) {
                const int e = wn * 32 + nf * 8 + g;
                const char* p = bB + e * (FH_B_STR * 2) + (kk * 16 + 2 * t) * 2;
                b0[nf] = *reinterpret_cast<const uint32_t*>(p);
                b1[nf] = *reinterpret_cast<const uint32_t*>(p + 16);
            }
#pragma unroll
            for (int nf = 0; nf < 4; ++nf) {
                mma_f16(acc[nf], al[kk][0], al[kk][1], al[kk][2], al[kk][3], b0[nf], b1[nf]);
                mma_f16(acc[nf], ah[kk][0], ah[kk][1], ah[kk][2], ah[kk][3], b0[nf], b1[nf]);
            }
        }

        {
            const int r0 = wm * 16 + g;
#pragma unroll
            for (int nf = 0; nf < 4; ++nf) {
                const int col = nt * 128 + wn * 32 + nf * 8 + 2 * t;
                *reinterpret_cast<float2*>(&h3s[r0 * H3S + col]) =
                    make_float2(acc[nf][0], acc[nf][1]);
                *reinterpret_cast<float2*>(&h3s[(r0 + 8) * H3S + col]) =
                    make_float2(acc[nf][2], acc[nf][3]);
                s0 += acc[nf][0] + acc[nf][1];
                q0 += acc[nf][0] * acc[nf][0] + acc[nf][1] * acc[nf][1];
                s1 += acc[nf][2] + acc[nf][3];
                q1 += acc[nf][2] * acc[nf][2] + acc[nf][3] * acc[nf][3];
                acc[nf][0] = acc[nf][1] = acc[nf][2] = acc[nf][3] = 0.f;
            }
        }
        __syncthreads();

        if (nt + 2 < 8) {
            const int src_tile = nt + 2;
#pragma unroll
            for (int i = 0; i < 8; ++i) {
                const int linear = tid + i * 256;
                const int e = linear >> 4;
                const int c = linear & 15;
                CP_ASYNC16(sbase + FH_B_OFF + (src_tile & 1) * FH_B_SZ + e * (FH_B_STR * 2) + c * 16,
                           (const char*)WbH + (size_t)(src_tile * 128 + e) * KSLOT * 2 + c * 16);
            }
            CP_COMMIT();
        }
    }

    // deterministic row-stat reduction
    s0 += __shfl_xor_sync(0xffffffffu, s0, 1); s0 += __shfl_xor_sync(0xffffffffu, s0, 2);
    q0 += __shfl_xor_sync(0xffffffffu, q0, 1); q0 += __shfl_xor_sync(0xffffffffu, q0, 2);
    s1 += __shfl_xor_sync(0xffffffffu, s1, 1); s1 += __shfl_xor_sync(0xffffffffu, s1, 2);
    q1 += __shfl_xor_sync(0xffffffffu, q1, 1); q1 += __shfl_xor_sync(0xffffffffu, q1, 2);
    if (t == 0) {
        const int r0 = wm * 16 + g;
        part[wn * 32 + r0]           = s0;
        part[wn * 32 + r0 + 8]       = s1;
        part[128 + wn * 32 + r0]     = q0;
        part[128 + wn * 32 + r0 + 8] = q1;
    }
    __syncthreads();

    if (tid < 32) {
        float S = 0.f, Q = 0.f;
#pragma unroll
        for (int w = 0; w < 4; ++w) {
            S += part[w * 32 + tid];
            Q += part[128 + w * 32 + tid];
        }
        const float m = S * (1.f / DD);
        stat[tid]      = m;
        stat[32 + tid] = rsqrtf(Q * (1.f / DD) - m * m + 1e-5f);
    }
    __syncthreads();

    {
        const int row  = tid >> 3;
        const int grow = brow + row;
        const float m = stat[row];
        const float r = stat[32 + row];
        const float* h3r = &h3s[row * H3S];
        const float* xr  = xres + (size_t)grow * DD;
        float* outr      = out + (size_t)grow * DD;
#pragma unroll 4
        for (int j = 0; j < 32; ++j) {
            const int col = (tid & 7) * 4 + j * 32;
            const float4 h  = *reinterpret_cast<const float4*>(&h3r[col]);
            const float4 g4 = *reinterpret_cast<const float4*>(gg + col);
            const float4 b4 = *reinterpret_cast<const float4*>(bb + col);
            const float4 xv = *reinterpret_cast<const float4*>(xr + col);
            float4 o;
            o.x = fmaxf((h.x - m) * r * g4.x + b4.x + xv.x, 0.f);
            o.y = fmaxf((h.y - m) * r * g4.y + b4.y + xv.y, 0.f);
            o.z = fmaxf((h.z - m) * r * g4.z + b4.z + xv.z, 0.f);
            o.w = fmaxf((h.w - m) * r * g4.w + b4.w + xv.w, 0.f);
            *reinterpret_cast<float4*>(outr + col) = o;
        }
    }
}

// ---------------- split-K SIMT fp32 NN GEMM (weight prep only) ----------------
__global__ void __launch_bounds__(256, 1)
prep_gemm_splitk(const float* __restrict__ A, const float* __restrict__ B,
                 float* __restrict__ P, int M, int N, int K) {
    __shared__ float As[64][17];
    __shared__ float Bs[16][64];

    const int tid = threadIdx.x;
    const int tx = tid & 15;
    const int ty = tid >> 4;
    const int bm = blockIdx.y * 64;
    const int bn = blockIdx.x * 64;
    const int kchunk = K / NSPLIT;
    const int k0 = blockIdx.z * kchunk;

    float c[4][4];
#pragma unroll
    for (int q = 0; q < 4; ++q)
#pragma unroll
        for (int r = 0; r < 4; ++r) c[q][r] = 0.f;

    const int amm = tid >> 2;
    const int akk = (tid & 3) * 4;
    const int bc  = tid & 63;
    const int br0 = tid >> 6;

    for (int kt = 0; kt < kchunk; kt += 16) {
        const float4 va = *reinterpret_cast<const float4*>(
            A + (size_t)(bm + amm) * K + k0 + kt + akk);
        As[amm][akk + 0] = va.x;
        As[amm][akk + 1] = va.y;
        As[amm][akk + 2] = va.z;
        As[amm][akk + 3] = va.w;
#pragma unroll
        for (int j = 0; j < 4; ++j) {
            const int r = br0 + j * 4;
            Bs[r][bc] = B[(size_t)(k0 + kt + r) * N + bn + bc];
        }
        __syncthreads();

#pragma unroll
        for (int kk = 0; kk < 16; ++kk) {
            const float a0 = As[ty * 4 + 0][kk];
            const float a1 = As[ty * 4 + 1][kk];
            const float a2 = As[ty * 4 + 2][kk];
            const float a3 = As[ty * 4 + 3][kk];
            const float4 b = *reinterpret_cast<const float4*>(&Bs[kk][tx * 4]);
            c[0][0] += a0 * b.x; c[0][1] += a0 * b.y; c[0][2] += a0 * b.z; c[0][3] += a0 * b.w;
            c[1][0] += a1 * b.x; c[1][1] += a1 * b.y; c[1][2] += a1 * b.z; c[1][3] += a1 * b.w;
            c[2][0] += a2 * b.x; c[2][1] += a2 * b.y; c[2][2] += a2 * b.z; c[2][3] += a2 * b.w;
            c[3][0] += a3 * b.x; c[3][1] += a3 * b.y; c[3][2] += a3 * b.z; c[3][3] += a3 * b.w;
        }
        __syncthreads();
    }

    float* Pb = P + (size_t)blockIdx.z * M * N;
#pragma unroll
    for (int q = 0; q < 4; ++q) {
        const int row = bm + ty * 4 + q;
        *reinterpret_cast<float4*>(Pb + (size_t)row * N + bn + tx * 4) =
            make_float4(c[q][0], c[q][1], c[q][2], c[q][3]);
    }
}

__global__ void reduce_partials_h(const float* __restrict__ P, __half* __restrict__ C, int total) {
    const int i = blockIdx.x * 256 + threadIdx.x;
    if (i >= total) return;
    float s = 0.f;
#pragma unroll
    for (int ss = 0; ss < NSPLIT; ++ss) s += P[(size_t)ss * total + i];
    C[i] = __float2half_rn(s);
}

// ---------------- fused LN + logits GEMM + softmax pass1 (R10 shape, 256 thr) ----------------
__global__ void __launch_bounds__(256, 1)
gemm_ln_logits(const float* __restrict__ X, const float* __restrict__ Wag,
               const float* __restrict__ wsum, const float* __restrict__ cb,
               float* __restrict__ L) {
    __shared__ float As[2][128][20];
    __shared__ float Bs[2][128][20];
    __shared__ float sm_mean[128];
    __shared__ float sm_rstd[128];
    __shared__ float pm_part[4][KSLOT];
    __shared__ float ps_part[4][KSLOT];

    const int tid  = threadIdx.x;
    const int lane = tid & 31;
    const int warp = tid >> 5;
    const int wm   = warp & 3;
    const int wn   = warp >> 2;
    const int g    = lane >> 2;
    const int t    = lane & 3;

    const int brow = blockIdx.y * 128;
    const int K = DD;

    float acc[2][8][4];
#pragma unroll
    for (int i = 0; i < 2; ++i)
#pragma unroll
        for (int j = 0; j < 8; ++j)
#pragma unroll
            for (int q = 0; q < 4; ++q) acc[i][j][q] = 0.f;

    const int r0 = tid >> 2;
    const int kc = (tid & 3) * 4;
    const int ktiles = K / 16;

    float sumA = 0.f, sqA = 0.f, sumB = 0.f, sqB = 0.f;

    auto issue = [&](int kt, int s) {
        const float* Ag = X + (size_t)(brow + r0) * K + kt * 16 + kc;
        const float* Bg = Wag + (size_t)r0 * K + kt * 16 + kc;
        CP_ASYNC16(smem_u32(&As[s][r0][kc]),      Ag);
        CP_ASYNC16(smem_u32(&As[s][r0 + 64][kc]), Ag + (size_t)64 * K);
        CP_ASYNC16(smem_u32(&Bs[s][r0][kc]),      Bg);
        CP_ASYNC16(smem_u32(&Bs[s][r0 + 64][kc]), Bg + (size_t)64 * K);
    };

    issue(0, 0);
    CP_COMMIT();

    for (int kt = 0; kt < ktiles; ++kt) {
        const int cur = kt & 1;
        if (kt + 1 < ktiles) {
            issue(kt + 1, (kt + 1) & 1);
            CP_COMMIT();
            CP_WAIT(1);
        } else {
            CP_WAIT(0);
        }
        __syncthreads();

        {
            const float4 va = *reinterpret_cast<const float4*>(&As[cur][r0][kc]);
            const float4 vb = *reinterpret_cast<const float4*>(&As[cur][r0 + 64][kc]);
            sumA += va.x + va.y + va.z + va.w;
            sqA  += va.x * va.x + va.y * va.y + va.z * va.z + va.w * va.w;
            sumB += vb.x + vb.y + vb.z + vb.w;
            sqB  += vb.x * vb.x + vb.y * vb.y + vb.z * vb.z + vb.w * vb.w;
        }

        uint32_t ah[2][4], al[2][4];
#pragma unroll
        for (int mt = 0; mt < 2; ++mt) {
            const int row = wm * 32 + mt * 16 + g;
            const float2 v0 = *reinterpret_cast<const float2*>(&As[cur][row][2 * t]);
            const float2 v1 = *reinterpret_cast<const float2*>(&As[cur][row + 8][2 * t]);
            const float2 v2 = *reinterpret_cast<const float2*>(&As[cur][row][2 * t + 8]);
            const float2 v3 = *reinterpret_cast<const float2*>(&As[cur][row + 8][2 * t + 8]);
            split_f16(v0, ah[mt][0], al[mt][0]);
            split_f16(v1, ah[mt][1], al[mt][1]);
            split_f16(v2, ah[mt][2], al[mt][2]);
            split_f16(v3, ah[mt][3], al[mt][3]);
        }

        uint32_t bh[8][2];
#pragma unroll
        for (int nt = 0; nt < 8; ++nt) {
            const int col = wn * 64 + nt * 8 + g;
            bh[nt][0] = pack_f16(*reinterpret_cast<const float2*>(&Bs[cur][col][2 * t]));
            bh[nt][1] = pack_f16(*reinterpret_cast<const float2*>(&Bs[cur][col][2 * t + 8]));
        }

#pragma unroll
        for (int mt = 0; mt < 2; ++mt)
#pragma unroll
            for (int nt = 0; nt < 8; ++nt) {
                mma_f16(acc[mt][nt], al[mt][0], al[mt][1], al[mt][2], al[mt][3],
                        bh[nt][0], bh[nt][1]);
                mma_f16(acc[mt][nt], ah[mt][0], ah[mt][1], ah[mt][2], ah[mt][3],
                        bh[nt][0], bh[nt][1]);
            }
        __syncthreads();
    }

#pragma unroll
    for (int o = 1; o <= 2; o <<= 1) {
        sumA += __shfl_xor_sync(0xffffffffu, sumA, o);
        sqA  += __shfl_xor_sync(0xffffffffu, sqA, o);
        sumB += __shfl_xor_sync(0xffffffffu, sumB, o);
        sqB  += __shfl_xor_sync(0xffffffffu, sqB, o);
    }
    if ((tid & 3) == 0) {
        const float mA = sumA * (1.f / DD);
        const float mB = sumB * (1.f / DD);
        sm_mean[r0]      = mA;
        sm_mean[r0 + 64] = mB;
        sm_rstd[r0]      = rsqrtf(sqA * (1.f / DD) - mA * mA + 1e-5f);
        sm_rstd[r0 + 64] = rsqrtf(sqB * (1.f / DD) - mB * mB + 1e-5f);
    }
    __syncthreads();

    // apply LN affine; keep transformed values in acc for softmax partials
#pragma unroll
    for (int mt = 0; mt < 2; ++mt) {
        const int lrow0 = wm * 32 + mt * 16 + g;
        const float m0 = sm_mean[lrow0],     r0s = sm_rstd[lrow0];
        const float m1 = sm_mean[lrow0 + 8], r1s = sm_rstd[lrow0 + 8];
        const int row = brow + lrow0;
#pragma unroll
        for (int nt = 0; nt < 8; ++nt) {
            const int col = wn * 64 + nt * 8 + t * 2;
            const float ws0 = wsum[col], ws1 = wsum[col + 1];
            const float cb0 = cb[col],   cb1 = cb[col + 1];
            acc[mt][nt][0] = r0s * (acc[mt][nt][0] - m0 * ws0) + cb0;
            acc[mt][nt][1] = r0s * (acc[mt][nt][1] - m0 * ws1) + cb1;
            acc[mt][nt][2] = r1s * (acc[mt][nt][2] - m1 * ws0) + cb0;
            acc[mt][nt][3] = r1s * (acc[mt][nt][3] - m1 * ws1) + cb1;
            *reinterpret_cast<float2*>(L + (size_t)row * KSLOT + col) =
                make_float2(acc[mt][nt][0], acc[mt][nt][1]);
            *reinterpret_cast<float2*>(L + (size_t)(row + 8) * KSLOT + col) =
                make_float2(acc[mt][nt][2], acc[mt][nt][3]);
        }
    }

    // softmax pass1: per-column (k) max + scaled exp-sum over this 128-row chunk
#pragma unroll
    for (int nt = 0; nt < 8; ++nt) {
        float m0 = fmaxf(fmaxf(acc[0][nt][0], acc[0][nt][2]), fmaxf(acc[1][nt][0], acc[1][nt][2]));
        float m1 = fmaxf(fmaxf(acc[0][nt][1], acc[0][nt][3]), fmaxf(acc[1][nt][1], acc[1][nt][3]));
#pragma unroll
        for (int o = 4; o <= 16; o <<= 1) {
            m0 = fmaxf(m0, __shfl_xor_sync(0xffffffffu, m0, o));
            m1 = fmaxf(m1, __shfl_xor_sync(0xffffffffu, m1, o));
        }
        float sc0 = __expf(acc[0][nt][0] - m0) + __expf(acc[0][nt][2] - m0) +
                    __expf(acc[1][nt][0] - m0) + __expf(acc[1][nt][2] - m0);
        float sc1 = __expf(acc[0][nt][1] - m1) + __expf(acc[0][nt][3] - m1) +
                    __expf(acc[1][nt][1] - m1) + __expf(acc[1][nt][3] - m1);
#pragma unroll
        for (int o = 4; o <= 16; o <<= 1) {
            sc0 += __shfl_xor_sync(0xffffffffu, sc0, o);
            sc1 += __shfl_xor_sync(0xffffffffu, sc1, o);
        }
        if (lane < 4) {  // g == 0
            const int col = wn * 64 + nt * 8 + 2 * t;
            pm_part[wm][col]     = m0;
            ps_part[wm][col]     = sc0;
            pm_part[wm][col + 1] = m1;
            ps_part[wm][col + 1] = sc1;
        }
    }
    __syncthreads();

    if (tid < KSLOT) {
        float M = fmaxf(fmaxf(pm_part[0][tid], pm_part[1][tid]),
                        fmaxf(pm_part[2][tid], pm_part[3][tid]));
        float S = ps_part[0][tid] * __expf(pm_part[0][tid] - M) +
                  ps_part[1][tid] * __expf(pm_part[1][tid] - M) +
                  ps_part[2][tid] * __expf(pm_part[2][tid] - M) +
                  ps_part[3][tid] * __expf(pm_part[3][tid] - M);
        g_pm[blockIdx.y * KSLOT + tid] = M;
        g_ps[blockIdx.y * KSLOT + tid] = S;
    }
}

// ---------------- prep: reduce Wa partials + build Wag/wsum/cb (ba folded in) ----------------
__global__ void prep_wag_kernel(const float* __restrict__ Pa, const float* __restrict__ gg,
                                const float* __restrict__ bb, const float* __restrict__ w0,
                                const float* __restrict__ b_in,
                                float* __restrict__ Wag, float* __restrict__ wsum,
                                float* __restrict__ cb) {
    const int k = blockIdx.x;
    const int tid = threadIdx.x;  // 256
    float4 w = make_float4(0.f, 0.f, 0.f, 0.f);
#pragma unroll
    for (int ss = 0; ss < NSPLIT; ++ss) {
        const float4 p = reinterpret_cast<const float4*>(
            Pa + (size_t)ss * KSLOT * DD + (size_t)k * DD)[tid];
        w.x += p.x; w.y += p.y; w.z += p.z; w.w += p.w;
    }
    const float4 g4 = reinterpret_cast<const float4*>(gg)[tid];
    const float4 b4 = reinterpret_cast<const float4*>(bb)[tid];
    float4 wg;
    wg.x = w.x * g4.x; wg.y = w.y * g4.y; wg.z = w.z * g4.z; wg.w = w.w * g4.w;
    reinterpret_cast<float4*>(Wag + (size_t)k * DD)[tid] = wg;

    const float4 w0v = reinterpret_cast<const float4*>(w0 + (size_t)k * DD)[tid];
    const float4 biv = reinterpret_cast<const float4*>(b_in)[tid];

    float s = wg.x + wg.y + wg.z + wg.w;
    float c = w.x * b4.x + w.y * b4.y + w.z * b4.z + w.w * b4.w
            + w0v.x * biv.x + w0v.y * biv.y + w0v.z * biv.z + w0v.w * biv.w;
#pragma unroll
    for (int o = 16; o > 0; o >>= 1) {
        s += __shfl_xor_sync(0xffffffffu, s, o);
        c += __shfl_xor_sync(0xffffffffu, c, o);
    }
    __shared__ float rs[8], rc[8];
    if ((tid & 31) == 0) { rs[tid >> 5] = s; rc[tid >> 5] = c; }
    __syncthreads();
    if (tid == 0) {
        float S = 0.f, C = 0.f;
#pragma unroll
        for (int i = 0; i < 8; ++i) { S += rs[i]; C += rc[i]; }
        wsum[k] = S;
        cb[k] = C;
    }
}

// ---------------- launch ----------------
extern "C" void kernel_launch(void* const* d_in, const int* in_sizes, int n_in,
                              void* d_out, int out_size) {
    const float* x     = (const float*)d_in[0];
    const float* ln_g  = (const float*)d_in[1];
    const float* ln_b  = (const float*)d_in[2];
    const float* w_in  = (const float*)d_in[3];
    const float* b_in  = (const float*)d_in[4];
    const float* w0    = (const float*)d_in[5];
    const float* w1    = (const float*)d_in[6];
    const float* w_out = (const float*)d_in[7];
    const float* og    = (const float*)d_in[8];
    const float* ob    = (const float*)d_in[9];
    float* out = (float*)d_out;

    static float* logits = nullptr;
    static float* Pa = nullptr; static float* Pb = nullptr;
    static float* Wag = nullptr;
    static float* wsum = nullptr; static float* cb = nullptr;
    static __half* WbH = nullptr;
    static cudaStream_t s2 = nullptr;
    static cudaEvent_t evF = nullptr, evJ = nullptr;
    if (!logits) {
        cudaGetSymbolAddress((void**)&logits, g_logits);
        cudaGetSymbolAddress((void**)&Pa, g_Pa);
        cudaGetSymbolAddress((void**)&Pb, g_Pb);
        cudaGetSymbolAddress((void**)&Wag, g_Wag);
        cudaGetSymbolAddress((void**)&wsum, g_wsum);
        cudaGetSymbolAddress((void**)&cb, g_cb);
        cudaGetSymbolAddress((void**)&WbH, g_WbH);
        cudaFuncSetAttribute(h3_final_fused, cudaFuncAttributeMaxDynamicSharedMemorySize, FH_SMEM);
        cudaStreamCreateWithFlags(&s2, cudaStreamNonBlocking);
        cudaEventCreateWithFlags(&evF, cudaEventDisableTiming);
        cudaEventCreateWithFlags(&evJ, cudaEventDisableTiming);
    }

    // ---- fork: WbH prep chain on s2 (independent until the fused kernel) ----
    cudaEventRecord(evF, 0);
    cudaStreamWaitEvent(s2, evF, 0);
    prep_gemm_splitk<<<dim3(KSLOT / 64, DD / 64, NSPLIT), 256, 0, s2>>>(w_out, w1, Pb, DD, KSLOT, DD);
    reduce_partials_h<<<(DD * KSLOT + 255) / 256, 256, 0, s2>>>(Pb, WbH, DD * KSLOT);
    cudaEventRecord(evJ, s2);

    // ---- main stream: Wa chain + logits path ----
    prep_gemm_splitk<<<dim3(DD / 64, KSLOT / 64, NSPLIT), 256>>>(w0, w_in, Pa, KSLOT, DD, DD);
    prep_wag_kernel<<<KSLOT, 256>>>(Pa, ln_g, ln_b, w0, b_in, Wag, wsum, cb);

    // logits = LN(x) @ Wa^T + ba, fused, also emits softmax chunk partials
    gemm_ln_logits<<<dim3(1, MTOT / 128), 256>>>(x, Wag, wsum, cb, logits);

    // ---- join, then fused: softmax(pass2+norm) + h3 + LN + residual + relu ----
    cudaStreamWaitEvent(0, evJ, 0);
    h3_final_fused<<<MTOT / 32, 256, FH_SMEM>>>(logits, WbH, x, og, ob, out);
}

// round 14
// speedup vs baseline: 1.0857x; 1.0857x over previous
#include <cuda_runtime.h>
#include <cuda_fp16.h>
#include <cstdint>
#include <cstddef>

#define BB 8
#define NN 4096
#define DD 1024
#define KSLOT 128
#define MTOT (BB * NN)        // 32768
#define NCHUNK 32             // NN / 128
#define NSPLIT 8              // split-K for weight prep

// ---------------- scratch ----------------
__device__ float g_logits[(size_t)MTOT * KSLOT];// 16 MiB (raw logits)
__device__ float g_pm[BB * NCHUNK * KSLOT];
__device__ float g_ps[BB * NCHUNK * KSLOT];
__device__ float g_M[BB * KSLOT];
__device__ float g_S[BB * KSLOT];               // stores 1/S
__device__ float g_Pa[(size_t)NSPLIT * KSLOT * DD];
__device__ float g_Pb[(size_t)NSPLIT * DD * KSLOT];
__device__ float g_Wag[(size_t)KSLOT * DD];
__device__ float g_wsum[KSLOT];
__device__ float g_cb[KSLOT];
__device__ __half g_WbH[(size_t)DD * KSLOT];    // (w_out @ w1) rounded to fp16, [e,k]

#define NEG_INF __int_as_float(0xff800000)

// ---------------- fp16 split helpers ----------------
__device__ __forceinline__ uint32_t pack_f16(float2 v) {
    __half2 h = __floats2half2_rn(v.x, v.y);
    return *reinterpret_cast<uint32_t*>(&h);
}

__device__ __forceinline__ void split_f16(float2 v, uint32_t& hi, uint32_t& lo) {
    __half2 h = __floats2half2_rn(v.x, v.y);
    hi = *reinterpret_cast<uint32_t*>(&h);
    const float2 hf = __half22float2(h);
    __half2 l = __floats2half2_rn(v.x - hf.x, v.y - hf.y);
    lo = *reinterpret_cast<uint32_t*>(&l);
}

// m16n8k16 fp16 MMA, fp32 accumulate
__device__ __forceinline__ void mma_f16(float* c,
                                        uint32_t a0, uint32_t a1, uint32_t a2, uint32_t a3,
                                        uint32_t b0, uint32_t b1) {
    asm volatile(
        "mma.sync.aligned.m16n8k16.row.col.f32.f16.f16.f32 "
        "{%0,%1,%2,%3}, {%4,%5,%6,%7}, {%8,%9}, {%0,%1,%2,%3};"
        : "+f"(c[0]), "+f"(c[1]), "+f"(c[2]), "+f"(c[3])
        : "r"(a0), "r"(a1), "r"(a2), "r"(a3), "r"(b0), "r"(b1));
}

__device__ __forceinline__ uint32_t smem_u32(const void* p) {
    uint32_t addr;
    asm("{ .reg .u64 tmp; cvta.to.shared.u64 tmp, %1; cvt.u32.u64 %0, tmp; }"
        : "=r"(addr) : "l"(p));
    return addr;
}

#define CP_ASYNC16(dst, src) \
    asm volatile("cp.async.cg.shared.global [%0], [%1], 16;\n" ::"r"(dst), "l"(src))
#define CP_COMMIT() asm volatile("cp.async.commit_group;\n")
#define CP_WAIT(N_) asm volatile("cp.async.wait_group %0;\n" ::"n"(N_))

// ================= fused h3 GEMM + softmax-normalize + LN + residual + relu =================
// block = 32 rows of logits (BM=32), full N=1024 columns, K=128. 256 threads (R10 shape).
#define H3S 1036
#define FH_A_OFF   132608               // 32*1036*4
#define FH_A_STR   132
#define FH_B_OFF   149504               // FH_A_OFF + 32*132*4
#define FH_B_STR   136
#define FH_B_SZ    34816                // 128*136*2
#define FH_PART_OFF 219136              // FH_B_OFF + 2*FH_B_SZ
#define FH_STAT_OFF 220160              // + 256 floats of partials
#define FH_SMEM     220416              // + mean[32]+rstd[32]

__global__ void __launch_bounds__(256, 1)
h3_final_fused(const float* __restrict__ A, const __half* __restrict__ WbH,
               const float* __restrict__ xres, const float* __restrict__ gg,
               const float* __restrict__ bb, float* __restrict__ out) {
    extern __shared__ char sm[];
    const uint32_t sbase = smem_u32(sm);
    float* h3s = reinterpret_cast<float*>(sm);
    float* As  = reinterpret_cast<float*>(sm + FH_A_OFF);
    float* part = reinterpret_cast<float*>(sm + FH_PART_OFF);
    float* stat = reinterpret_cast<float*>(sm + FH_STAT_OFF);

    const int tid  = threadIdx.x;
    const int warp = tid >> 5;
    const int lane = tid & 31;
    const int wm   = warp & 1;
    const int wn   = warp >> 1;
    const int g    = lane >> 2;
    const int t    = lane & 3;
    const int brow = blockIdx.x * 32;

    part[tid] = 0.f;

    // issue A stage (32 x 128 fp32 raw logits) + B tile 0
#pragma unroll
    for (int i = 0; i < 4; ++i) {
        const int linear = tid + i * 256;
        const int row = linear >> 5;
        const int c   = linear & 31;
        CP_ASYNC16(sbase + FH_A_OFF + row * (FH_A_STR * 4) + c * 16,
                   (const char*)A + (size_t)(brow + row) * KSLOT * 4 + c * 16);
    }
#pragma unroll
    for (int i = 0; i < 8; ++i) {
        const int linear = tid + i * 256;
        const int e = linear >> 4;
        const int c = linear & 15;
        CP_ASYNC16(sbase + FH_B_OFF + e * (FH_B_STR * 2) + c * 16,
                   (const char*)WbH + (size_t)e * KSLOT * 2 + c * 16);
    }
    CP_COMMIT();
#pragma unroll
    for (int i = 0; i < 8; ++i) {
        const int linear = tid + i * 256;
        const int e = linear >> 4;
        const int c = linear & 15;
        CP_ASYNC16(sbase + FH_B_OFF + FH_B_SZ + e * (FH_B_STR * 2) + c * 16,
                   (const char*)WbH + (size_t)(128 + e) * KSLOT * 2 + c * 16);
    }
    CP_COMMIT();

    uint32_t ah[8][4], al[8][4];
    float acc[4][4];
#pragma unroll
    for (int nf = 0; nf < 4; ++nf)
#pragma unroll
        for (int q = 0; q < 4; ++q) acc[nf][q] = 0.f;
    float s0 = 0.f, q0 = 0.f, s1 = 0.f, q1 = 0.f;

    for (int nt = 0; nt < 8; ++nt) {
        if (nt < 6) { CP_WAIT(1); } else { CP_WAIT(0); }
        __syncthreads();

        if (nt == 0) {
            // softmax-normalize A tile in place: p = exp(l - M)*invS, then L1 over k
            {
                const int b = brow >> 12;
                const int row = tid >> 3;
                const int c0 = (tid & 7) * 16;
                float* ar = &As[row * FH_A_STR + c0];
                float pv[16];
                float tot = 0.f;
#pragma unroll
                for (int j = 0; j < 16; ++j) {
                    const int k = c0 + j;
                    pv[j] = __expf(ar[j] - g_M[b * KSLOT + k]) * g_S[b * KSLOT + k];
                    tot += pv[j];
                }
                tot += __shfl_xor_sync(0xffffffffu, tot, 1);
                tot += __shfl_xor_sync(0xffffffffu, tot, 2);
                tot += __shfl_xor_sync(0xffffffffu, tot, 4);
                const float inv = 1.f / (1e-9f + tot);
#pragma unroll
                for (int j = 0; j < 16; ++j) ar[j] = pv[j] * inv;
            }
            __syncthreads();

            // convert this warp's A fragments once (rows wm*16+g, +8; all K)
            const int r0 = wm * 16 + g;
#pragma unroll
            for (int kk = 0; kk < 8; ++kk) {
                const int kb = kk * 16 + 2 * t;
                const float2 v0 = *reinterpret_cast<const float2*>(&As[r0 * FH_A_STR + kb]);
                const float2 v1 = *reinterpret_cast<const float2*>(&As[(r0 + 8) * FH_A_STR + kb]);
                const float2 v2 = *reinterpret_cast<const float2*>(&As[r0 * FH_A_STR + kb + 8]);
                const float2 v3 = *reinterpret_cast<const float2*>(&As[(r0 + 8) * FH_A_STR + kb + 8]);
                split_f16(v0, ah[kk][0], al[kk][0]);
                split_f16(v1, ah[kk][1], al[kk][1]);
                split_f16(v2, ah[kk][2], al[kk][2]);
                split_f16(v3, ah[kk][3], al[kk][3]);
            }
        }

        const char* bB = sm + FH_B_OFF + (nt & 1) * FH_B_SZ;
#pragma unroll
        for (int kk = 0; kk < 8; ++kk) {
            uint32_t b0[4], b1[4];
#pragma unroll
            for (int nf = 0; nf < 4; ++nf) {
                const int e = wn * 32 + nf * 8 + g;
                const char* p = bB + e * (FH_B_STR * 2) + (kk * 16 + 2 * t) * 2;
                b0[nf] = *reinterpret_cast<const uint32_t*>(p);
                b1[nf] = *reinterpret_cast<const uint32_t*>(p + 16);
            }
#pragma unroll
            for (int nf = 0; nf < 4; ++nf) {
                mma_f16(acc[nf], al[kk][0], al[kk][1], al[kk][2], al[kk][3], b0[nf], b1[nf]);
                mma_f16(acc[nf], ah[kk][0], ah[kk][1], ah[kk][2], ah[kk][3], b0[nf], b1[nf]);
            }
        }

        {
            const int r0 = wm * 16 + g;
#pragma unroll
            for (int nf = 0; nf < 4; ++nf) {
                const int col = nt * 128 + wn * 32 + nf * 8 + 2 * t;
                *reinterpret_cast<float2*>(&h3s[r0 * H3S + col]) =
                    make_float2(acc[nf][0], acc[nf][1]);
                *reinterpret_cast<float2*>(&h3s[(r0 + 8) * H3S + col]) =
                    make_float2(acc[nf][2], acc[nf][3]);
                s0 += acc[nf][0] + acc[nf][1];
                q0 += acc[nf][0] * acc[nf][0] + acc[nf][1] * acc[nf][1];
                s1 += acc[nf][2] + acc[nf][3];
                q1 += acc[nf][2] * acc[nf][2] + acc[nf][3] * acc[nf][3];
                acc[nf][0] = acc[nf][1] = acc[nf][2] = acc[nf][3] = 0.f;
            }
        }
        __syncthreads();

        if (nt + 2 < 8) {
            const int src_tile = nt + 2;
#pragma unroll
            for (int i = 0; i < 8; ++i) {
                const int linear = tid + i * 256;
                const int e = linear >> 4;
                const int c = linear & 15;
                CP_ASYNC16(sbase + FH_B_OFF + (src_tile & 1) * FH_B_SZ + e * (FH_B_STR * 2) + c * 16,
                           (const char*)WbH + (size_t)(src_tile * 128 + e) * KSLOT * 2 + c * 16);
            }
            CP_COMMIT();
        }
    }

    // deterministic row-stat reduction: over t via shfl, then over wn via smem
    s0 += __shfl_xor_sync(0xffffffffu, s0, 1); s0 += __shfl_xor_sync(0xffffffffu, s0, 2);
    q0 += __shfl_xor_sync(0xffffffffu, q0, 1); q0 += __shfl_xor_sync(0xffffffffu, q0, 2);
    s1 += __shfl_xor_sync(0xffffffffu, s1, 1); s1 += __shfl_xor_sync(0xffffffffu, s1, 2);
    q1 += __shfl_xor_sync(0xffffffffu, q1, 1); q1 += __shfl_xor_sync(0xffffffffu, q1, 2);
    if (t == 0) {
        const int r0 = wm * 16 + g;
        part[wn * 32 + r0]           = s0;
        part[wn * 32 + r0 + 8]       = s1;
        part[128 + wn * 32 + r0]     = q0;
        part[128 + wn * 32 + r0 + 8] = q1;
    }
    __syncthreads();

    if (tid < 32) {
        float S = 0.f, Q = 0.f;
#pragma unroll
        for (int w = 0; w < 4; ++w) {
            S += part[w * 32 + tid];
            Q += part[128 + w * 32 + tid];
        }
        const float m = S * (1.f / DD);
        stat[tid]      = m;
        stat[32 + tid] = rsqrtf(Q * (1.f / DD) - m * m + 1e-5f);
    }
    __syncthreads();

    {
        const int row  = tid >> 3;
        const int grow = brow + row;
        const float m = stat[row];
        const float r = stat[32 + row];
        const float* h3r = &h3s[row * H3S];
        const float* xr  = xres + (size_t)grow * DD;
        float* outr      = out + (size_t)grow * DD;
#pragma unroll 4
        for (int j = 0; j < 32; ++j) {
            const int col = (tid & 7) * 4 + j * 32;
            const float4 h  = *reinterpret_cast<const float4*>(&h3r[col]);
            const float4 g4 = *reinterpret_cast<const float4*>(gg + col);
            const float4 b4 = *reinterpret_cast<const float4*>(bb + col);
            const float4 xv = *reinterpret_cast<const float4*>(xr + col);
            float4 o;
            o.x = fmaxf((h.x - m) * r * g4.x + b4.x + xv.x, 0.f);
            o.y = fmaxf((h.y - m) * r * g4.y + b4.y + xv.y, 0.f);
            o.z = fmaxf((h.z - m) * r * g4.z + b4.z + xv.z, 0.f);
            o.w = fmaxf((h.w - m) * r * g4.w + b4.w + xv.w, 0.f);
            *reinterpret_cast<float4*>(outr + col) = o;
        }
    }
}

// ---------------- split-K SIMT fp32 NN GEMM (weight prep only) ----------------
__global__ void __launch_bounds__(256, 1)
prep_gemm_splitk(const float* __restrict__ A, const float* __restrict__ B,
                 float* __restrict__ P, int M, int N, int K) {
    __shared__ float As[64][17];
    __shared__ float Bs[16][64];

    const int tid = threadIdx.x;
    const int tx = tid & 15;
    const int ty = tid >> 4;
    const int bm = blockIdx.y * 64;
    const int bn = blockIdx.x * 64;
    const int kchunk = K / NSPLIT;
    const int k0 = blockIdx.z * kchunk;

    float c[4][4];
#pragma unroll
    for (int q = 0; q < 4; ++q)
#pragma unroll
        for (int r = 0; r < 4; ++r) c[q][r] = 0.f;

    const int amm = tid >> 2;
    const int akk = (tid & 3) * 4;
    const int bc  = tid & 63;
    const int br0 = tid >> 6;

    for (int kt = 0; kt < kchunk; kt += 16) {
        const float4 va = *reinterpret_cast<const float4*>(
            A + (size_t)(bm + amm) * K + k0 + kt + akk);
        As[amm][akk + 0] = va.x;
        As[amm][akk + 1] = va.y;
        As[amm][akk + 2] = va.z;
        As[amm][akk + 3] = va.w;
#pragma unroll
        for (int j = 0; j < 4; ++j) {
            const int r = br0 + j * 4;
            Bs[r][bc] = B[(size_t)(k0 + kt + r) * N + bn + bc];
        }
        __syncthreads();

#pragma unroll
        for (int kk = 0; kk < 16; ++kk) {
            const float a0 = As[ty * 4 + 0][kk];
            const float a1 = As[ty * 4 + 1][kk];
            const float a2 = As[ty * 4 + 2][kk];
            const float a3 = As[ty * 4 + 3][kk];
            const float4 b = *reinterpret_cast<const float4*>(&Bs[kk][tx * 4]);
            c[0][0] += a0 * b.x; c[0][1] += a0 * b.y; c[0][2] += a0 * b.z; c[0][3] += a0 * b.w;
            c[1][0] += a1 * b.x; c[1][1] += a1 * b.y; c[1][2] += a1 * b.z; c[1][3] += a1 * b.w;
            c[2][0] += a2 * b.x; c[2][1] += a2 * b.y; c[2][2] += a2 * b.z; c[2][3] += a2 * b.w;
            c[3][0] += a3 * b.x; c[3][1] += a3 * b.y; c[3][2] += a3 * b.z; c[3][3] += a3 * b.w;
        }
        __syncthreads();
    }

    float* Pb = P + (size_t)blockIdx.z * M * N;
#pragma unroll
    for (int q = 0; q < 4; ++q) {
        const int row = bm + ty * 4 + q;
        *reinterpret_cast<float4*>(Pb + (size_t)row * N + bn + tx * 4) =
            make_float4(c[q][0], c[q][1], c[q][2], c[q][3]);
    }
}

__global__ void reduce_partials_h(const float* __restrict__ P, __half* __restrict__ C, int total) {
    const int i = blockIdx.x * 256 + threadIdx.x;
    if (i >= total) return;
    float s = 0.f;
#pragma unroll
    for (int ss = 0; ss < NSPLIT; ++ss) s += P[(size_t)ss * total + i];
    C[i] = __float2half_rn(s);
}

// ---------------- fused LN + logits GEMM + softmax pass1 (R10 shape, 256 thr) ----------------
__global__ void __launch_bounds__(256, 1)
gemm_ln_logits(const float* __restrict__ X, const float* __restrict__ Wag,
               const float* __restrict__ wsum, const float* __restrict__ cb,
               float* __restrict__ L) {
    __shared__ float As[2][128][20];
    __shared__ float Bs[2][128][20];
    __shared__ float sm_mean[128];
    __shared__ float sm_rstd[128];
    __shared__ float pm_part[4][KSLOT];
    __shared__ float ps_part[4][KSLOT];

    const int tid  = threadIdx.x;
    const int lane = tid & 31;
    const int warp = tid >> 5;
    const int wm   = warp & 3;
    const int wn   = warp >> 2;
    const int g    = lane >> 2;
    const int t    = lane & 3;

    const int brow = blockIdx.y * 128;
    const int K = DD;

    float acc[2][8][4];
#pragma unroll
    for (int i = 0; i < 2; ++i)
#pragma unroll
        for (int j = 0; j < 8; ++j)
#pragma unroll
            for (int q = 0; q < 4; ++q) acc[i][j][q] = 0.f;

    const int r0 = tid >> 2;
    const int kc = (tid & 3) * 4;
    const int ktiles = K / 16;

    float sumA = 0.f, sqA = 0.f, sumB = 0.f, sqB = 0.f;

    auto issue = [&](int kt, int s) {
        const float* Ag = X + (size_t)(brow + r0) * K + kt * 16 + kc;
        const float* Bg = Wag + (size_t)r0 * K + kt * 16 + kc;
        CP_ASYNC16(smem_u32(&As[s][r0][kc]),      Ag);
        CP_ASYNC16(smem_u32(&As[s][r0 + 64][kc]), Ag + (size_t)64 * K);
        CP_ASYNC16(smem_u32(&Bs[s][r0][kc]),      Bg);
        CP_ASYNC16(smem_u32(&Bs[s][r0 + 64][kc]), Bg + (size_t)64 * K);
    };

    issue(0, 0);
    CP_COMMIT();

    for (int kt = 0; kt < ktiles; ++kt) {
        const int cur = kt & 1;
        if (kt + 1 < ktiles) {
            issue(kt + 1, (kt + 1) & 1);
            CP_COMMIT();
            CP_WAIT(1);
        } else {
            CP_WAIT(0);
        }
        __syncthreads();

        {
            const float4 va = *reinterpret_cast<const float4*>(&As[cur][r0][kc]);
            const float4 vb = *reinterpret_cast<const float4*>(&As[cur][r0 + 64][kc]);
            sumA += va.x + va.y + va.z + va.w;
            sqA  += va.x * va.x + va.y * va.y + va.z * va.z + va.w * va.w;
            sumB += vb.x + vb.y + vb.z + vb.w;
            sqB  += vb.x * vb.x + vb.y * vb.y + vb.z * vb.z + vb.w * vb.w;
        }

        uint32_t ah[2][4], al[2][4];
#pragma unroll
        for (int mt = 0; mt < 2; ++mt) {
            const int row = wm * 32 + mt * 16 + g;
            const float2 v0 = *reinterpret_cast<const float2*>(&As[cur][row][2 * t]);
            const float2 v1 = *reinterpret_cast<const float2*>(&As[cur][row + 8][2 * t]);
            const float2 v2 = *reinterpret_cast<const float2*>(&As[cur][row][2 * t + 8]);
            const float2 v3 = *reinterpret_cast<const float2*>(&As[cur][row + 8][2 * t + 8]);
            split_f16(v0, ah[mt][0], al[mt][0]);
            split_f16(v1, ah[mt][1], al[mt][1]);
            split_f16(v2, ah[mt][2], al[mt][2]);
            split_f16(v3, ah[mt][3], al[mt][3]);
        }

        uint32_t bh[8][2];
#pragma unroll
        for (int nt = 0; nt < 8; ++nt) {
            const int col = wn * 64 + nt * 8 + g;
            bh[nt][0] = pack_f16(*reinterpret_cast<const float2*>(&Bs[cur][col][2 * t]));
            bh[nt][1] = pack_f16(*reinterpret_cast<const float2*>(&Bs[cur][col][2 * t + 8]));
        }

#pragma unroll
        for (int mt = 0; mt < 2; ++mt)
#pragma unroll
            for (int nt = 0; nt < 8; ++nt) {
                mma_f16(acc[mt][nt], al[mt][0], al[mt][1], al[mt][2], al[mt][3],
                        bh[nt][0], bh[nt][1]);
                mma_f16(acc[mt][nt], ah[mt][0], ah[mt][1], ah[mt][2], ah[mt][3],
                        bh[nt][0], bh[nt][1]);
            }
        __syncthreads();
    }

#pragma unroll
    for (int o = 1; o <= 2; o <<= 1) {
        sumA += __shfl_xor_sync(0xffffffffu, sumA, o);
        sqA  += __shfl_xor_sync(0xffffffffu, sqA, o);
        sumB += __shfl_xor_sync(0xffffffffu, sumB, o);
        sqB  += __shfl_xor_sync(0xffffffffu, sqB, o);
    }
    if ((tid & 3) == 0) {
        const float mA = sumA * (1.f / DD);
        const float mB = sumB * (1.f / DD);
        sm_mean[r0]      = mA;
        sm_mean[r0 + 64] = mB;
        sm_rstd[r0]      = rsqrtf(sqA * (1.f / DD) - mA * mA + 1e-5f);
        sm_rstd[r0 + 64] = rsqrtf(sqB * (1.f / DD) - mB * mB + 1e-5f);
    }
    __syncthreads();

    // apply LN affine; keep transformed values in acc for softmax partials
#pragma unroll
    for (int mt = 0; mt < 2; ++mt) {
        const int lrow0 = wm * 32 + mt * 16 + g;
        const float m0 = sm_mean[lrow0],     r0s = sm_rstd[lrow0];
        const float m1 = sm_mean[lrow0 + 8], r1s = sm_rstd[lrow0 + 8];
        const int row = brow + lrow0;
#pragma unroll
        for (int nt = 0; nt < 8; ++nt) {
            const int col = wn * 64 + nt * 8 + t * 2;
            const float ws0 = wsum[col], ws1 = wsum[col + 1];
            const float cb0 = cb[col],   cb1 = cb[col + 1];
            acc[mt][nt][0] = r0s * (acc[mt][nt][0] - m0 * ws0) + cb0;
            acc[mt][nt][1] = r0s * (acc[mt][nt][1] - m0 * ws1) + cb1;
            acc[mt][nt][2] = r1s * (acc[mt][nt][2] - m1 * ws0) + cb0;
            acc[mt][nt][3] = r1s * (acc[mt][nt][3] - m1 * ws1) + cb1;
            *reinterpret_cast<float2*>(L + (size_t)row * KSLOT + col) =
                make_float2(acc[mt][nt][0], acc[mt][nt][1]);
            *reinterpret_cast<float2*>(L + (size_t)(row + 8) * KSLOT + col) =
                make_float2(acc[mt][nt][2], acc[mt][nt][3]);
        }
    }

    // softmax pass1: per-column (k) max + scaled exp-sum over this 128-row chunk
#pragma unroll
    for (int nt = 0; nt < 8; ++nt) {
        float m0 = fmaxf(fmaxf(acc[0][nt][0], acc[0][nt][2]), fmaxf(acc[1][nt][0], acc[1][nt][2]));
        float m1 = fmaxf(fmaxf(acc[0][nt][1], acc[0][nt][3]), fmaxf(acc[1][nt][1], acc[1][nt][3]));
#pragma unroll
        for (int o = 4; o <= 16; o <<= 1) {
            m0 = fmaxf(m0, __shfl_xor_sync(0xffffffffu, m0, o));
            m1 = fmaxf(m1, __shfl_xor_sync(0xffffffffu, m1, o));
        }
        float sc0 = __expf(acc[0][nt][0] - m0) + __expf(acc[0][nt][2] - m0) +
                    __expf(acc[1][nt][0] - m0) + __expf(acc[1][nt][2] - m0);
        float sc1 = __expf(acc[0][nt][1] - m1) + __expf(acc[0][nt][3] - m1) +
                    __expf(acc[1][nt][1] - m1) + __expf(acc[1][nt][3] - m1);
#pragma unroll
        for (int o = 4; o <= 16; o <<= 1) {
            sc0 += __shfl_xor_sync(0xffffffffu, sc0, o);
            sc1 += __shfl_xor_sync(0xffffffffu, sc1, o);
        }
        if (lane < 4) {  // g == 0
            const int col = wn * 64 + nt * 8 + 2 * t;
            pm_part[wm][col]     = m0;
            ps_part[wm][col]     = sc0;
            pm_part[wm][col + 1] = m1;
            ps_part[wm][col + 1] = sc1;
        }
    }
    __syncthreads();

    if (tid < KSLOT) {
        float M = fmaxf(fmaxf(pm_part[0][tid], pm_part[1][tid]),
                        fmaxf(pm_part[2][tid], pm_part[3][tid]));
        float S = ps_part[0][tid] * __expf(pm_part[0][tid] - M) +
                  ps_part[1][tid] * __expf(pm_part[1][tid] - M) +
                  ps_part[2][tid] * __expf(pm_part[2][tid] - M) +
                  ps_part[3][tid] * __expf(pm_part[3][tid] - M);
        g_pm[blockIdx.y * KSLOT + tid] = M;
        g_ps[blockIdx.y * KSLOT + tid] = S;
    }
}

// ---------------- prep: reduce Wa partials + build Wag/wsum/cb (ba folded in) ----------------
__global__ void prep_wag_kernel(const float* __restrict__ Pa, const float* __restrict__ gg,
                                const float* __restrict__ bb, const float* __restrict__ w0,
                                const float* __restrict__ b_in,
                                float* __restrict__ Wag, float* __restrict__ wsum,
                                float* __restrict__ cb) {
    const int k = blockIdx.x;
    const int tid = threadIdx.x;  // 256
    float4 w = make_float4(0.f, 0.f, 0.f, 0.f);
#pragma unroll
    for (int ss = 0; ss < NSPLIT; ++ss) {
        const float4 p = reinterpret_cast<const float4*>(
            Pa + (size_t)ss * KSLOT * DD + (size_t)k * DD)[tid];
        w.x += p.x; w.y += p.y; w.z += p.z; w.w += p.w;
    }
    const float4 g4 = reinterpret_cast<const float4*>(gg)[tid];
    const float4 b4 = reinterpret_cast<const float4*>(bb)[tid];
    float4 wg;
    wg.x = w.x * g4.x; wg.y = w.y * g4.y; wg.z = w.z * g4.z; wg.w = w.w * g4.w;
    reinterpret_cast<float4*>(Wag + (size_t)k * DD)[tid] = wg;

    const float4 w0v = reinterpret_cast<const float4*>(w0 + (size_t)k * DD)[tid];
    const float4 biv = reinterpret_cast<const float4*>(b_in)[tid];

    float s = wg.x + wg.y + wg.z + wg.w;
    float c = w.x * b4.x + w.y * b4.y + w.z * b4.z + w.w * b4.w
            + w0v.x * biv.x + w0v.y * biv.y + w0v.z * biv.z + w0v.w * biv.w;
#pragma unroll
    for (int o = 16; o > 0; o >>= 1) {
        s += __shfl_xor_sync(0xffffffffu, s, o);
        c += __shfl_xor_sync(0xffffffffu, c, o);
    }
    __shared__ float rs[8], rc[8];
    if ((tid & 31) == 0) { rs[tid >> 5] = s; rc[tid >> 5] = c; }
    __syncthreads();
    if (tid == 0) {
        float S = 0.f, C = 0.f;
#pragma unroll
        for (int i = 0; i < 8; ++i) { S += rs[i]; C += rc[i]; }
        wsum[k] = S;
        cb[k] = C;
    }
}

// ---------------- softmax pass2: combine chunk partials (stores 1/S) ----------------
__global__ void softmax_pass2() {
    const int b = blockIdx.x;
    const int k = threadIdx.x;  // 128
    float M = NEG_INF;
#pragma unroll
    for (int c = 0; c < NCHUNK; ++c) M = fmaxf(M, g_pm[(b * NCHUNK + c) * KSLOT + k]);
    float S = 0.f;
#pragma unroll
    for (int c = 0; c < NCHUNK; ++c)
        S += g_ps[(b * NCHUNK + c) * KSLOT + k] * __expf(g_pm[(b * NCHUNK + c) * KSLOT + k] - M);
    g_M[b * KSLOT + k] = M;
    g_S[b * KSLOT + k] = 1.f / S;
}

// ---------------- launch ----------------
extern "C" void kernel_launch(void* const* d_in, const int* in_sizes, int n_in,
                              void* d_out, int out_size) {
    const float* x     = (const float*)d_in[0];
    const float* ln_g  = (const float*)d_in[1];
    const float* ln_b  = (const float*)d_in[2];
    const float* w_in  = (const float*)d_in[3];
    const float* b_in  = (const float*)d_in[4];
    const float* w0    = (const float*)d_in[5];
    const float* w1    = (const float*)d_in[6];
    const float* w_out = (const float*)d_in[7];
    const float* og    = (const float*)d_in[8];
    const float* ob    = (const float*)d_in[9];
    float* out = (float*)d_out;

    static float* logits = nullptr;
    static float* Pa = nullptr; static float* Pb = nullptr;
    static float* Wag = nullptr;
    static float* wsum = nullptr; static float* cb = nullptr;
    static __half* WbH = nullptr;
    static cudaStream_t s2 = nullptr;
    static cudaEvent_t evF = nullptr, evJ = nullptr;
    if (!logits) {
        cudaGetSymbolAddress((void**)&logits, g_logits);
        cudaGetSymbolAddress((void**)&Pa, g_Pa);
        cudaGetSymbolAddress((void**)&Pb, g_Pb);
        cudaGetSymbolAddress((void**)&Wag, g_Wag);
        cudaGetSymbolAddress((void**)&wsum, g_wsum);
        cudaGetSymbolAddress((void**)&cb, g_cb);
        cudaGetSymbolAddress((void**)&WbH, g_WbH);
        cudaFuncSetAttribute(h3_final_fused, cudaFuncAttributeMaxDynamicSharedMemorySize, FH_SMEM);
        cudaStreamCreateWithFlags(&s2, cudaStreamNonBlocking);
        cudaEventCreateWithFlags(&evF, cudaEventDisableTiming);
        cudaEventCreateWithFlags(&evJ, cudaEventDisableTiming);
    }

    // ---- fork: WbH prep chain on s2 (independent until the fused kernel) ----
    cudaEventRecord(evF, 0);
    cudaStreamWaitEvent(s2, evF, 0);
    prep_gemm_splitk<<<dim3(KSLOT / 64, DD / 64, NSPLIT), 256, 0, s2>>>(w_out, w1, Pb, DD, KSLOT, DD);
    reduce_partials_h<<<(DD * KSLOT + 255) / 256, 256, 0, s2>>>(Pb, WbH, DD * KSLOT);
    cudaEventRecord(evJ, s2);

    // ---- main stream: Wa chain + logits path ----
    prep_gemm_splitk<<<dim3(DD / 64, KSLOT / 64, NSPLIT), 256>>>(w0, w_in, Pa, KSLOT, DD, DD);
    prep_wag_kernel<<<KSLOT, 256>>>(Pa, ln_g, ln_b, w0, b_in, Wag, wsum, cb);

    // logits = LN(x) @ Wa^T + ba, fused, also emits softmax chunk partials
    gemm_ln_logits<<<dim3(1, MTOT / 128), 256>>>(x, Wag, wsum, cb, logits);
    softmax_pass2<<<BB, 128>>>();

    // ---- join, then fused: softmax-normalize + h3 + LN + residual + relu ----
    cudaStreamWaitEvent(0, evJ, 0);
    h3_final_fused<<<MTOT / 32, 256, FH_SMEM>>>(logits, WbH, x, og, ob, out);
}

// round 15
// speedup vs baseline: 1.3249x; 1.2203x over previous
#include <cuda_runtime.h>
#include <cuda_fp16.h>
#include <cstdint>
#include <cstddef>

#define BB 8
#define NN 4096
#define DD 1024
#define KSLOT 128
#define MTOT (BB * NN)        // 32768
#define NCHUNK 32             // NN / 128
#define NSPLIT 8              // split-K for weight prep

// ---------------- scratch ----------------
__device__ float g_logits[(size_t)MTOT * KSLOT];// 16 MiB (raw logits)
__device__ float g_pm[BB * NCHUNK * KSLOT];
__device__ float g_ps[BB * NCHUNK * KSLOT];
__device__ float g_M[BB * KSLOT];
__device__ float g_S[BB * KSLOT];               // stores 1/S
__device__ float g_Pa[(size_t)NSPLIT * KSLOT * DD];
__device__ float g_Pb[(size_t)NSPLIT * DD * KSLOT];
__device__ float g_wsum[KSLOT];
__device__ float g_cb[KSLOT];
__device__ __half g_Wah[(size_t)KSLOT * DD];    // rn_f16(Wa*g)  [k,d]
__device__ __half g_WbH[(size_t)DD * KSLOT];    // (w_out @ w1) rounded to fp16, [e,k]

#define NEG_INF __int_as_float(0xff800000)

// ---------------- fp16 split helpers ----------------
__device__ __forceinline__ void split_f16(float2 v, uint32_t& hi, uint32_t& lo) {
    __half2 h = __floats2half2_rn(v.x, v.y);
    hi = *reinterpret_cast<uint32_t*>(&h);
    const float2 hf = __half22float2(h);
    __half2 l = __floats2half2_rn(v.x - hf.x, v.y - hf.y);
    lo = *reinterpret_cast<uint32_t*>(&l);
}

// m16n8k16 fp16 MMA, fp32 accumulate
__device__ __forceinline__ void mma_f16(float* c,
                                        uint32_t a0, uint32_t a1, uint32_t a2, uint32_t a3,
                                        uint32_t b0, uint32_t b1) {
    asm volatile(
        "mma.sync.aligned.m16n8k16.row.col.f32.f16.f16.f32 "
        "{%0,%1,%2,%3}, {%4,%5,%6,%7}, {%8,%9}, {%0,%1,%2,%3};"
        : "+f"(c[0]), "+f"(c[1]), "+f"(c[2]), "+f"(c[3])
        : "r"(a0), "r"(a1), "r"(a2), "r"(a3), "r"(b0), "r"(b1));
}

__device__ __forceinline__ uint32_t smem_u32(const void* p) {
    uint32_t addr;
    asm("{ .reg .u64 tmp; cvta.to.shared.u64 tmp, %1; cvt.u32.u64 %0, tmp; }"
        : "=r"(addr) : "l"(p));
    return addr;
}

#define CP_ASYNC16(dst, src) \
    asm volatile("cp.async.cg.shared.global [%0], [%1], 16;\n" ::"r"(dst), "l"(src))
#define CP_COMMIT() asm volatile("cp.async.commit_group;\n")
#define CP_WAIT(N_) asm volatile("cp.async.wait_group %0;\n" ::"n"(N_))

// ================= fused h3 GEMM + softmax-normalize + LN + residual + relu =================
// (unchanged from R14 — proven shape)
#define H3S 1036
#define FH_A_OFF   132608               // 32*1036*4
#define FH_A_STR   132
#define FH_B_OFF   149504               // FH_A_OFF + 32*132*4
#define FH_B_STR   136
#define FH_B_SZ    34816                // 128*136*2
#define FH_PART_OFF 219136              // FH_B_OFF + 2*FH_B_SZ
#define FH_STAT_OFF 220160              // + 256 floats of partials
#define FH_SMEM     220416              // + mean[32]+rstd[32]

__global__ void __launch_bounds__(256, 1)
h3_final_fused(const float* __restrict__ A, const __half* __restrict__ WbH,
               const float* __restrict__ xres, const float* __restrict__ gg,
               const float* __restrict__ bb, float* __restrict__ out) {
    extern __shared__ char sm[];
    const uint32_t sbase = smem_u32(sm);
    float* h3s = reinterpret_cast<float*>(sm);
    float* As  = reinterpret_cast<float*>(sm + FH_A_OFF);
    float* part = reinterpret_cast<float*>(sm + FH_PART_OFF);
    float* stat = reinterpret_cast<float*>(sm + FH_STAT_OFF);

    const int tid  = threadIdx.x;
    const int warp = tid >> 5;
    const int lane = tid & 31;
    const int wm   = warp & 1;
    const int wn   = warp >> 1;
    const int g    = lane >> 2;
    const int t    = lane & 3;
    const int brow = blockIdx.x * 32;

    part[tid] = 0.f;

#pragma unroll
    for (int i = 0; i < 4; ++i) {
        const int linear = tid + i * 256;
        const int row = linear >> 5;
        const int c   = linear & 31;
        CP_ASYNC16(sbase + FH_A_OFF + row * (FH_A_STR * 4) + c * 16,
                   (const char*)A + (size_t)(brow + row) * KSLOT * 4 + c * 16);
    }
#pragma unroll
    for (int i = 0; i < 8; ++i) {
        const int linear = tid + i * 256;
        const int e = linear >> 4;
        const int c = linear & 15;
        CP_ASYNC16(sbase + FH_B_OFF + e * (FH_B_STR * 2) + c * 16,
                   (const char*)WbH + (size_t)e * KSLOT * 2 + c * 16);
    }
    CP_COMMIT();
#pragma unroll
    for (int i = 0; i < 8; ++i) {
        const int linear = tid + i * 256;
        const int e = linear >> 4;
        const int c = linear & 15;
        CP_ASYNC16(sbase + FH_B_OFF + FH_B_SZ + e * (FH_B_STR * 2) + c * 16,
                   (const char*)WbH + (size_t)(128 + e) * KSLOT * 2 + c * 16);
    }
    CP_COMMIT();

    uint32_t ah[8][4], al[8][4];
    float acc[4][4];
#pragma unroll
    for (int nf = 0; nf < 4; ++nf)
#pragma unroll
        for (int q = 0; q < 4; ++q) acc[nf][q] = 0.f;
    float s0 = 0.f, q0 = 0.f, s1 = 0.f, q1 = 0.f;

    for (int nt = 0; nt < 8; ++nt) {
        if (nt < 6) { CP_WAIT(1); } else { CP_WAIT(0); }
        __syncthreads();

        if (nt == 0) {
            {
                const int b = brow >> 12;
                const int row = tid >> 3;
                const int c0 = (tid & 7) * 16;
                float* ar = &As[row * FH_A_STR + c0];
                float pv[16];
                float tot = 0.f;
#pragma unroll
                for (int j = 0; j < 16; ++j) {
                    const int k = c0 + j;
                    pv[j] = __expf(ar[j] - g_M[b * KSLOT + k]) * g_S[b * KSLOT + k];
                    tot += pv[j];
                }
                tot += __shfl_xor_sync(0xffffffffu, tot, 1);
                tot += __shfl_xor_sync(0xffffffffu, tot, 2);
                tot += __shfl_xor_sync(0xffffffffu, tot, 4);
                const float inv = 1.f / (1e-9f + tot);
#pragma unroll
                for (int j = 0; j < 16; ++j) ar[j] = pv[j] * inv;
            }
            __syncthreads();

            const int r0 = wm * 16 + g;
#pragma unroll
            for (int kk = 0; kk < 8; ++kk) {
                const int kb = kk * 16 + 2 * t;
                const float2 v0 = *reinterpret_cast<const float2*>(&As[r0 * FH_A_STR + kb]);
                const float2 v1 = *reinterpret_cast<const float2*>(&As[(r0 + 8) * FH_A_STR + kb]);
                const float2 v2 = *reinterpret_cast<const float2*>(&As[r0 * FH_A_STR + kb + 8]);
                const float2 v3 = *reinterpret_cast<const float2*>(&As[(r0 + 8) * FH_A_STR + kb + 8]);
                split_f16(v0, ah[kk][0], al[kk][0]);
                split_f16(v1, ah[kk][1], al[kk][1]);
                split_f16(v2, ah[kk][2], al[kk][2]);
                split_f16(v3, ah[kk][3], al[kk][3]);
            }
        }

        const char* bB = sm + FH_B_OFF + (nt & 1) * FH_B_SZ;
#pragma unroll
        for (int kk = 0; kk < 8; ++kk) {
            uint32_t b0[4], b1[4];
#pragma unroll
            for (int nf = 0; nf < 4; ++nf) {
                const int e = wn * 32 + nf * 8 + g;
                const char* p = bB + e * (FH_B_STR * 2) + (kk * 16 + 2 * t) * 2;
                b0[nf] = *reinterpret_cast<const uint32_t*>(p);
                b1[nf] = *reinterpret_cast<const uint32_t*>(p + 16);
            }
#pragma unroll
            for (int nf = 0; nf < 4; ++nf) {
                mma_f16(acc[nf], al[kk][0], al[kk][1], al[kk][2], al[kk][3], b0[nf], b1[nf]);
                mma_f16(acc[nf], ah[kk][0], ah[kk][1], ah[kk][2], ah[kk][3], b0[nf], b1[nf]);
            }
        }

        {
            const int r0 = wm * 16 + g;
#pragma unroll
            for (int nf = 0; nf < 4; ++nf) {
                const int col = nt * 128 + wn * 32 + nf * 8 + 2 * t;
                *reinterpret_cast<float2*>(&h3s[r0 * H3S + col]) =
                    make_float2(acc[nf][0], acc[nf][1]);
                *reinterpret_cast<float2*>(&h3s[(r0 + 8) * H3S + col]) =
                    make_float2(acc[nf][2], acc[nf][3]);
                s0 += acc[nf][0] + acc[nf][1];
                q0 += acc[nf][0] * acc[nf][0] + acc[nf][1] * acc[nf][1];
                s1 += acc[nf][2] + acc[nf][3];
                q1 += acc[nf][2] * acc[nf][2] + acc[nf][3] * acc[nf][3];
                acc[nf][0] = acc[nf][1] = acc[nf][2] = acc[nf][3] = 0.f;
            }
        }
        __syncthreads();

        if (nt + 2 < 8) {
            const int src_tile = nt + 2;
#pragma unroll
            for (int i = 0; i < 8; ++i) {
                const int linear = tid + i * 256;
                const int e = linear >> 4;
                const int c = linear & 15;
                CP_ASYNC16(sbase + FH_B_OFF + (src_tile & 1) * FH_B_SZ + e * (FH_B_STR * 2) + c * 16,
                           (const char*)WbH + (size_t)(src_tile * 128 + e) * KSLOT * 2 + c * 16);
            }
            CP_COMMIT();
        }
    }

    s0 += __shfl_xor_sync(0xffffffffu, s0, 1); s0 += __shfl_xor_sync(0xffffffffu, s0, 2);
    q0 += __shfl_xor_sync(0xffffffffu, q0, 1); q0 += __shfl_xor_sync(0xffffffffu, q0, 2);
    s1 += __shfl_xor_sync(0xffffffffu, s1, 1); s1 += __shfl_xor_sync(0xffffffffu, s1, 2);
    q1 += __shfl_xor_sync(0xffffffffu, q1, 1); q1 += __shfl_xor_sync(0xffffffffu, q1, 2);
    if (t == 0) {
        const int r0 = wm * 16 + g;
        part[wn * 32 + r0]           = s0;
        part[wn * 32 + r0 + 8]       = s1;
        part[128 + wn * 32 + r0]     = q0;
        part[128 + wn * 32 + r0 + 8] = q1;
    }
    __syncthreads();

    if (tid < 32) {
        float S = 0.f, Q = 0.f;
#pragma unroll
        for (int w = 0; w < 4; ++w) {
            S += part[w * 32 + tid];
            Q += part[128 + w * 32 + tid];
        }
        const float m = S * (1.f / DD);
        stat[tid]      = m;
        stat[32 + tid] = rsqrtf(Q * (1.f / DD) - m * m + 1e-5f);
    }
    __syncthreads();

    {
        const int row  = tid >> 3;
        const int grow = brow + row;
        const float m = stat[row];
        const float r = stat[32 + row];
        const float* h3r = &h3s[row * H3S];
        const float* xr  = xres + (size_t)grow * DD;
        float* outr      = out + (size_t)grow * DD;
#pragma unroll 4
        for (int j = 0; j < 32; ++j) {
            const int col = (tid & 7) * 4 + j * 32;
            const float4 h  = *reinterpret_cast<const float4*>(&h3r[col]);
            const float4 g4 = *reinterpret_cast<const float4*>(gg + col);
            const float4 b4 = *reinterpret_cast<const float4*>(bb + col);
            const float4 xv = *reinterpret_cast<const float4*>(xr + col);
            float4 o;
            o.x = fmaxf((h.x - m) * r * g4.x + b4.x + xv.x, 0.f);
            o.y = fmaxf((h.y - m) * r * g4.y + b4.y + xv.y, 0.f);
            o.z = fmaxf((h.z - m) * r * g4.z + b4.z + xv.z, 0.f);
            o.w = fmaxf((h.w - m) * r * g4.w + b4.w + xv.w, 0.f);
            *reinterpret_cast<float4*>(outr + col) = o;
        }
    }
}

// ---------------- split-K SIMT fp32 NN GEMM (weight prep only) ----------------
__global__ void __launch_bounds__(256, 1)
prep_gemm_splitk(const float* __restrict__ A, const float* __restrict__ B,
                 float* __restrict__ P, int M, int N, int K) {
    __shared__ float As[64][17];
    __shared__ float Bs[16][64];

    const int tid = threadIdx.x;
    const int tx = tid & 15;
    const int ty = tid >> 4;
    const int bm = blockIdx.y * 64;
    const int bn = blockIdx.x * 64;
    const int kchunk = K / NSPLIT;
    const int k0 = blockIdx.z * kchunk;

    float c[4][4];
#pragma unroll
    for (int q = 0; q < 4; ++q)
#pragma unroll
        for (int r = 0; r < 4; ++r) c[q][r] = 0.f;

    const int amm = tid >> 2;
    const int akk = (tid & 3) * 4;
    const int bc  = tid & 63;
    const int br0 = tid >> 6;

    for (int kt = 0; kt < kchunk; kt += 16) {
        const float4 va = *reinterpret_cast<const float4*>(
            A + (size_t)(bm + amm) * K + k0 + kt + akk);
        As[amm][akk + 0] = va.x;
        As[amm][akk + 1] = va.y;
        As[amm][akk + 2] = va.z;
        As[amm][akk + 3] = va.w;
#pragma unroll
        for (int j = 0; j < 4; ++j) {
            const int r = br0 + j * 4;
            Bs[r][bc] = B[(size_t)(k0 + kt + r) * N + bn + bc];
        }
        __syncthreads();

#pragma unroll
        for (int kk = 0; kk < 16; ++kk) {
            const float a0 = As[ty * 4 + 0][kk];
            const float a1 = As[ty * 4 + 1][kk];
            const float a2 = As[ty * 4 + 2][kk];
            const float a3 = As[ty * 4 + 3][kk];
            const float4 b = *reinterpret_cast<const float4*>(&Bs[kk][tx * 4]);
            c[0][0] += a0 * b.x; c[0][1] += a0 * b.y; c[0][2] += a0 * b.z; c[0][3] += a0 * b.w;
            c[1][0] += a1 * b.x; c[1][1] += a1 * b.y; c[1][2] += a1 * b.z; c[1][3] += a1 * b.w;
            c[2][0] += a2 * b.x; c[2][1] += a2 * b.y; c[2][2] += a2 * b.z; c[2][3] += a2 * b.w;
            c[3][0] += a3 * b.x; c[3][1] += a3 * b.y; c[3][2] += a3 * b.z; c[3][3] += a3 * b.w;
        }
        __syncthreads();
    }

    float* Pb = P + (size_t)blockIdx.z * M * N;
#pragma unroll
    for (int q = 0; q < 4; ++q) {
        const int row = bm + ty * 4 + q;
        *reinterpret_cast<float4*>(Pb + (size_t)row * N + bn + tx * 4) =
            make_float4(c[q][0], c[q][1], c[q][2], c[q][3]);
    }
}

__global__ void reduce_partials_h(const float* __restrict__ P, __half* __restrict__ C, int total) {
    const int i = blockIdx.x * 256 + threadIdx.x;
    if (i >= total) return;
    float s = 0.f;
#pragma unroll
    for (int ss = 0; ss < NSPLIT; ++ss) s += P[(size_t)ss * total + i];
    C[i] = __float2half_rn(s);
}

// ---------------- fused LN + logits GEMM + softmax pass1 (pre-split smem) ----------------
#define LG_STR 24   // halves per smem row (all-distinct banks for fragment LDS)
__global__ void __launch_bounds__(256, 2)
gemm_ln_logits(const float* __restrict__ X, const __half* __restrict__ Wah,
               const float* __restrict__ wsum, const float* __restrict__ cb,
               float* __restrict__ L) {
    __shared__ __half Ah[2][128][LG_STR];
    __shared__ __half Al[2][128][LG_STR];
    __shared__ __half Bh[2][128][LG_STR];
    __shared__ float sm_mean[128];
    __shared__ float sm_rstd[128];
    __shared__ float pm_part[4][KSLOT];
    __shared__ float ps_part[4][KSLOT];

    const int tid  = threadIdx.x;
    const int lane = tid & 31;
    const int warp = tid >> 5;
    const int wm   = warp & 3;
    const int wn   = warp >> 2;
    const int g    = lane >> 2;
    const int t    = lane & 3;

    const int brow = blockIdx.y * 128;

    float acc[2][8][4];
#pragma unroll
    for (int i = 0; i < 2; ++i)
#pragma unroll
        for (int j = 0; j < 8; ++j)
#pragma unroll
            for (int q = 0; q < 4; ++q) acc[i][j][q] = 0.f;

    const int r0 = tid >> 2;         // 0..63 (A rows r0, r0+64)
    const int kc = (tid & 3) * 4;    // 0,4,8,12
    const int brB = tid >> 1;        // 0..127 (B rows)
    const int bcB = (tid & 1) * 8;   // halves 0 or 8

    float sumA = 0.f, sqA = 0.f, sumB = 0.f, sqB = 0.f;

    float4 pa0, pa1;
    auto ldgA = [&](int kt) {
        pa0 = *reinterpret_cast<const float4*>(X + (size_t)(brow + r0) * DD + kt * 16 + kc);
        pa1 = *reinterpret_cast<const float4*>(X + (size_t)(brow + r0 + 64) * DD + kt * 16 + kc);
    };
    auto stsA = [&](int s) {
        // split + store row r0
        __half2 h0 = __floats2half2_rn(pa0.x, pa0.y);
        __half2 h1 = __floats2half2_rn(pa0.z, pa0.w);
        float2 f0 = __half22float2(h0), f1 = __half22float2(h1);
        __half2 l0 = __floats2half2_rn(pa0.x - f0.x, pa0.y - f0.y);
        __half2 l1 = __floats2half2_rn(pa0.z - f1.x, pa0.w - f1.y);
        *reinterpret_cast<__half2*>(&Ah[s][r0][kc])     = h0;
        *reinterpret_cast<__half2*>(&Ah[s][r0][kc + 2]) = h1;
        *reinterpret_cast<__half2*>(&Al[s][r0][kc])     = l0;
        *reinterpret_cast<__half2*>(&Al[s][r0][kc + 2]) = l1;
        sumA += pa0.x + pa0.y + pa0.z + pa0.w;
        sqA  += pa0.x * pa0.x + pa0.y * pa0.y + pa0.z * pa0.z + pa0.w * pa0.w;
        // row r0+64
        __half2 h2 = __floats2half2_rn(pa1.x, pa1.y);
        __half2 h3 = __floats2half2_rn(pa1.z, pa1.w);
        float2 f2 = __half22float2(h2), f3 = __half22float2(h3);
        __half2 l2 = __floats2half2_rn(pa1.x - f2.x, pa1.y - f2.y);
        __half2 l3 = __floats2half2_rn(pa1.z - f3.x, pa1.w - f3.y);
        *reinterpret_cast<__half2*>(&Ah[s][r0 + 64][kc])     = h2;
        *reinterpret_cast<__half2*>(&Ah[s][r0 + 64][kc + 2]) = h3;
        *reinterpret_cast<__half2*>(&Al[s][r0 + 64][kc])     = l2;
        *reinterpret_cast<__half2*>(&Al[s][r0 + 64][kc + 2]) = l3;
        sumB += pa1.x + pa1.y + pa1.z + pa1.w;
        sqB  += pa1.x * pa1.x + pa1.y * pa1.y + pa1.z * pa1.z + pa1.w * pa1.w;
    };
    auto issueB = [&](int kt, int s) {
        CP_ASYNC16(smem_u32(&Bh[s][brB][bcB]),
                   Wah + (size_t)brB * DD + kt * 16 + bcB);
    };

    ldgA(0);
    issueB(0, 0);
    CP_COMMIT();

    for (int kt = 0; kt < DD / 16; ++kt) {
        const int cur = kt & 1;
        const bool more = (kt + 1 < DD / 16);
        if (more) {
            issueB(kt + 1, cur ^ 1);
            CP_COMMIT();
        }
        stsA(cur);
        if (more) ldgA(kt + 1);
        if (more) { CP_WAIT(1); } else { CP_WAIT(0); }
        __syncthreads();

        uint32_t ah[2][4], al[2][4];
#pragma unroll
        for (int mt = 0; mt < 2; ++mt) {
            const int row = wm * 32 + mt * 16 + g;
            ah[mt][0] = *reinterpret_cast<const uint32_t*>(&Ah[cur][row][2 * t]);
            ah[mt][1] = *reinterpret_cast<const uint32_t*>(&Ah[cur][row + 8][2 * t]);
            ah[mt][2] = *reinterpret_cast<const uint32_t*>(&Ah[cur][row][2 * t + 8]);
            ah[mt][3] = *reinterpret_cast<const uint32_t*>(&Ah[cur][row + 8][2 * t + 8]);
            al[mt][0] = *reinterpret_cast<const uint32_t*>(&Al[cur][row][2 * t]);
            al[mt][1] = *reinterpret_cast<const uint32_t*>(&Al[cur][row + 8][2 * t]);
            al[mt][2] = *reinterpret_cast<const uint32_t*>(&Al[cur][row][2 * t + 8]);
            al[mt][3] = *reinterpret_cast<const uint32_t*>(&Al[cur][row + 8][2 * t + 8]);
        }

        uint32_t bh[8][2];
#pragma unroll
        for (int nt = 0; nt < 8; ++nt) {
            const int col = wn * 64 + nt * 8 + g;
            bh[nt][0] = *reinterpret_cast<const uint32_t*>(&Bh[cur][col][2 * t]);
            bh[nt][1] = *reinterpret_cast<const uint32_t*>(&Bh[cur][col][2 * t + 8]);
        }

#pragma unroll
        for (int mt = 0; mt < 2; ++mt)
#pragma unroll
            for (int nt = 0; nt < 8; ++nt) {
                mma_f16(acc[mt][nt], al[mt][0], al[mt][1], al[mt][2], al[mt][3],
                        bh[nt][0], bh[nt][1]);
                mma_f16(acc[mt][nt], ah[mt][0], ah[mt][1], ah[mt][2], ah[mt][3],
                        bh[nt][0], bh[nt][1]);
            }
        __syncthreads();
    }

#pragma unroll
    for (int o = 1; o <= 2; o <<= 1) {
        sumA += __shfl_xor_sync(0xffffffffu, sumA, o);
        sqA  += __shfl_xor_sync(0xffffffffu, sqA, o);
        sumB += __shfl_xor_sync(0xffffffffu, sumB, o);
        sqB  += __shfl_xor_sync(0xffffffffu, sqB, o);
    }
    if ((tid & 3) == 0) {
        const float mA = sumA * (1.f / DD);
        const float mB = sumB * (1.f / DD);
        sm_mean[r0]      = mA;
        sm_mean[r0 + 64] = mB;
        sm_rstd[r0]      = rsqrtf(sqA * (1.f / DD) - mA * mA + 1e-5f);
        sm_rstd[r0 + 64] = rsqrtf(sqB * (1.f / DD) - mB * mB + 1e-5f);
    }
    __syncthreads();

    // apply LN affine; keep transformed values in acc for softmax partials
#pragma unroll
    for (int mt = 0; mt < 2; ++mt) {
        const int lrow0 = wm * 32 + mt * 16 + g;
        const float m0 = sm_mean[lrow0],     r0s = sm_rstd[lrow0];
        const float m1 = sm_mean[lrow0 + 8], r1s = sm_rstd[lrow0 + 8];
        const int row = brow + lrow0;
#pragma unroll
        for (int nt = 0; nt < 8; ++nt) {
            const int col = wn * 64 + nt * 8 + t * 2;
            const float ws0 = wsum[col], ws1 = wsum[col + 1];
            const float cb0 = cb[col],   cb1 = cb[col + 1];
            acc[mt][nt][0] = r0s * (acc[mt][nt][0] - m0 * ws0) + cb0;
            acc[mt][nt][1] = r0s * (acc[mt][nt][1] - m0 * ws1) + cb1;
            acc[mt][nt][2] = r1s * (acc[mt][nt][2] - m1 * ws0) + cb0;
            acc[mt][nt][3] = r1s * (acc[mt][nt][3] - m1 * ws1) + cb1;
            *reinterpret_cast<float2*>(L + (size_t)row * KSLOT + col) =
                make_float2(acc[mt][nt][0], acc[mt][nt][1]);
            *reinterpret_cast<float2*>(L + (size_t)(row + 8) * KSLOT + col) =
                make_float2(acc[mt][nt][2], acc[mt][nt][3]);
        }
    }

    // softmax pass1: per-column (k) max + scaled exp-sum over this 128-row chunk
#pragma unroll
    for (int nt = 0; nt < 8; ++nt) {
        float m0 = fmaxf(fmaxf(acc[0][nt][0], acc[0][nt][2]), fmaxf(acc[1][nt][0], acc[1][nt][2]));
        float m1 = fmaxf(fmaxf(acc[0][nt][1], acc[0][nt][3]), fmaxf(acc[1][nt][1], acc[1][nt][3]));
#pragma unroll
        for (int o = 4; o <= 16; o <<= 1) {
            m0 = fmaxf(m0, __shfl_xor_sync(0xffffffffu, m0, o));
            m1 = fmaxf(m1, __shfl_xor_sync(0xffffffffu, m1, o));
        }
        float sc0 = __expf(acc[0][nt][0] - m0) + __expf(acc[0][nt][2] - m0) +
                    __expf(acc[1][nt][0] - m0) + __expf(acc[1][nt][2] - m0);
        float sc1 = __expf(acc[0][nt][1] - m1) + __expf(acc[0][nt][3] - m1) +
                    __expf(acc[1][nt][1] - m1) + __expf(acc[1][nt][3] - m1);
#pragma unroll
        for (int o = 4; o <= 16; o <<= 1) {
            sc0 += __shfl_xor_sync(0xffffffffu, sc0, o);
            sc1 += __shfl_xor_sync(0xffffffffu, sc1, o);
        }
        if (lane < 4) {  // g == 0
            const int col = wn * 64 + nt * 8 + 2 * t;
            pm_part[wm][col]     = m0;
            ps_part[wm][col]     = sc0;
            pm_part[wm][col + 1] = m1;
            ps_part[wm][col + 1] = sc1;
        }
    }
    __syncthreads();

    if (tid < KSLOT) {
        float M = fmaxf(fmaxf(pm_part[0][tid], pm_part[1][tid]),
                        fmaxf(pm_part[2][tid], pm_part[3][tid]));
        float S = ps_part[0][tid] * __expf(pm_part[0][tid] - M) +
                  ps_part[1][tid] * __expf(pm_part[1][tid] - M) +
                  ps_part[2][tid] * __expf(pm_part[2][tid] - M) +
                  ps_part[3][tid] * __expf(pm_part[3][tid] - M);
        g_pm[blockIdx.y * KSLOT + tid] = M;
        g_ps[blockIdx.y * KSLOT + tid] = S;
    }
}

// ---------------- prep: reduce Wa partials + build Wah/wsum/cb (ba folded in) ----------------
__global__ void prep_wag_kernel(const float* __restrict__ Pa, const float* __restrict__ gg,
                                const float* __restrict__ bb, const float* __restrict__ w0,
                                const float* __restrict__ b_in,
                                __half* __restrict__ Wah, float* __restrict__ wsum,
                                float* __restrict__ cb) {
    const int k = blockIdx.x;
    const int tid = threadIdx.x;  // 256
    float4 w = make_float4(0.f, 0.f, 0.f, 0.f);
#pragma unroll
    for (int ss = 0; ss < NSPLIT; ++ss) {
        const float4 p = reinterpret_cast<const float4*>(
            Pa + (size_t)ss * KSLOT * DD + (size_t)k * DD)[tid];
        w.x += p.x; w.y += p.y; w.z += p.z; w.w += p.w;
    }
    const float4 g4 = reinterpret_cast<const float4*>(gg)[tid];
    const float4 b4 = reinterpret_cast<const float4*>(bb)[tid];
    float4 wg;
    wg.x = w.x * g4.x; wg.y = w.y * g4.y; wg.z = w.z * g4.z; wg.w = w.w * g4.w;
    // store fp16 hi of Wag (the only form the logits GEMM consumes)
    __half2 wh0 = __floats2half2_rn(wg.x, wg.y);
    __half2 wh1 = __floats2half2_rn(wg.z, wg.w);
    *reinterpret_cast<__half2*>(Wah + (size_t)k * DD + 4 * tid)     = wh0;
    *reinterpret_cast<__half2*>(Wah + (size_t)k * DD + 4 * tid + 2) = wh1;

    const float4 w0v = reinterpret_cast<const float4*>(w0 + (size_t)k * DD)[tid];
    const float4 biv = reinterpret_cast<const float4*>(b_in)[tid];

    float s = wg.x + wg.y + wg.z + wg.w;
    float c = w.x * b4.x + w.y * b4.y + w.z * b4.z + w.w * b4.w
            + w0v.x * biv.x + w0v.y * biv.y + w0v.z * biv.z + w0v.w * biv.w;
#pragma unroll
    for (int o = 16; o > 0; o >>= 1) {
        s += __shfl_xor_sync(0xffffffffu, s, o);
        c += __shfl_xor_sync(0xffffffffu, c, o);
    }
    __shared__ float rs[8], rc[8];
    if ((tid & 31) == 0) { rs[tid >> 5] = s; rc[tid >> 5] = c; }
    __syncthreads();
    if (tid == 0) {
        float S = 0.f, C = 0.f;
#pragma unroll
        for (int i = 0; i < 8; ++i) { S += rs[i]; C += rc[i]; }
        wsum[k] = S;
        cb[k] = C;
    }
}

// ---------------- softmax pass2: combine chunk partials (stores 1/S) ----------------
__global__ void softmax_pass2() {
    const int b = blockIdx.x;
    const int k = threadIdx.x;  // 128
    float M = NEG_INF;
#pragma unroll
    for (int c = 0; c < NCHUNK; ++c) M = fmaxf(M, g_pm[(b * NCHUNK + c) * KSLOT + k]);
    float S = 0.f;
#pragma unroll
    for (int c = 0; c < NCHUNK; ++c)
        S += g_ps[(b * NCHUNK + c) * KSLOT + k] * __expf(g_pm[(b * NCHUNK + c) * KSLOT + k] - M);
    g_M[b * KSLOT + k] = M;
    g_S[b * KSLOT + k] = 1.f / S;
}

// ---------------- launch ----------------
extern "C" void kernel_launch(void* const* d_in, const int* in_sizes, int n_in,
                              void* d_out, int out_size) {
    const float* x     = (const float*)d_in[0];
    const float* ln_g  = (const float*)d_in[1];
    const float* ln_b  = (const float*)d_in[2];
    const float* w_in  = (const float*)d_in[3];
    const float* b_in  = (const float*)d_in[4];
    const float* w0    = (const float*)d_in[5];
    const float* w1    = (const float*)d_in[6];
    const float* w_out = (const float*)d_in[7];
    const float* og    = (const float*)d_in[8];
    const float* ob    = (const float*)d_in[9];
    float* out = (float*)d_out;

    static float* logits = nullptr;
    static float* Pa = nullptr; static float* Pb = nullptr;
    static float* wsum = nullptr; static float* cb = nullptr;
    static __half* Wah = nullptr; static __half* WbH = nullptr;
    static cudaStream_t s2 = nullptr;
    static cudaEvent_t evF = nullptr, evJ = nullptr;
    if (!logits) {
        cudaGetSymbolAddress((void**)&logits, g_logits);
        cudaGetSymbolAddress((void**)&Pa, g_Pa);
        cudaGetSymbolAddress((void**)&Pb, g_Pb);
        cudaGetSymbolAddress((void**)&wsum, g_wsum);
        cudaGetSymbolAddress((void**)&cb, g_cb);
        cudaGetSymbolAddress((void**)&Wah, g_Wah);
        cudaGetSymbolAddress((void**)&WbH, g_WbH);
        cudaFuncSetAttribute(h3_final_fused, cudaFuncAttributeMaxDynamicSharedMemorySize, FH_SMEM);
        cudaStreamCreateWithFlags(&s2, cudaStreamNonBlocking);
        cudaEventCreateWithFlags(&evF, cudaEventDisableTiming);
        cudaEventCreateWithFlags(&evJ, cudaEventDisableTiming);
    }

    // ---- fork: WbH prep chain on s2 (independent until the fused kernel) ----
    cudaEventRecord(evF, 0);
    cudaStreamWaitEvent(s2, evF, 0);
    prep_gemm_splitk<<<dim3(KSLOT / 64, DD / 64, NSPLIT), 256, 0, s2>>>(w_out, w1, Pb, DD, KSLOT, DD);
    reduce_partials_h<<<(DD * KSLOT + 255) / 256, 256, 0, s2>>>(Pb, WbH, DD * KSLOT);
    cudaEventRecord(evJ, s2);

    // ---- main stream: Wa chain + logits path ----
    prep_gemm_splitk<<<dim3(DD / 64, KSLOT / 64, NSPLIT), 256>>>(w0, w_in, Pa, KSLOT, DD, DD);
    prep_wag_kernel<<<KSLOT, 256>>>(Pa, ln_g, ln_b, w0, b_in, Wah, wsum, cb);

    // logits = LN(x) @ Wa^T + ba, fused, also emits softmax chunk partials
    gemm_ln_logits<<<dim3(1, MTOT / 128), 256>>>(x, Wah, wsum, cb, logits);
    softmax_pass2<<<BB, 128>>>();

    // ---- join, then fused: softmax-normalize + h3 + LN + residual + relu ----
    cudaStreamWaitEvent(0, evJ, 0);
    h3_final_fused<<<MTOT / 32, 256, FH_SMEM>>>(logits, WbH, x, og, ob, out);
}

// round 17
// speedup vs baseline: 1.5666x; 1.1824x over previous
#include <cuda_runtime.h>
#include <cuda_fp16.h>
#include <cstdint>
#include <cstddef>

#define BB 8
#define NN 4096
#define DD 1024
#define KSLOT 128
#define MTOT (BB * NN)        // 32768
#define NCHUNK 32             // NN / 128
#define NSPLIT 8              // split-K for weight prep

// ---------------- scratch ----------------
__device__ float g_logits[(size_t)MTOT * KSLOT];// 16 MiB (raw logits)
__device__ float g_pm[BB * NCHUNK * KSLOT];
__device__ float g_ps[BB * NCHUNK * KSLOT];
__device__ float g_M[BB * KSLOT];
__device__ float g_S[BB * KSLOT];               // stores 1/S
__device__ float g_Pa[(size_t)NSPLIT * KSLOT * DD];
__device__ float g_Pb[(size_t)NSPLIT * DD * KSLOT];
__device__ float g_wsum[KSLOT];
__device__ float g_cb[KSLOT];
__device__ __half g_Wah[(size_t)KSLOT * DD];    // rn_f16(Wa*g)  [k,d]
__device__ __half g_WbH[(size_t)DD * KSLOT];    // (w_out @ w1) rounded to fp16, [e,k]

#define NEG_INF __int_as_float(0xff800000)

// m16n8k16 fp16 MMA, fp32 accumulate
__device__ __forceinline__ void mma_f16(float* c,
                                        uint32_t a0, uint32_t a1, uint32_t a2, uint32_t a3,
                                        uint32_t b0, uint32_t b1) {
    asm volatile(
        "mma.sync.aligned.m16n8k16.row.col.f32.f16.f16.f32 "
        "{%0,%1,%2,%3}, {%4,%5,%6,%7}, {%8,%9}, {%0,%1,%2,%3};"
        : "+f"(c[0]), "+f"(c[1]), "+f"(c[2]), "+f"(c[3])
        : "r"(a0), "r"(a1), "r"(a2), "r"(a3), "r"(b0), "r"(b1));
}

__device__ __forceinline__ uint32_t smem_u32(const void* p) {
    uint32_t addr;
    asm("{ .reg .u64 tmp; cvta.to.shared.u64 tmp, %1; cvt.u32.u64 %0, tmp; }"
        : "=r"(addr) : "l"(p));
    return addr;
}

#define CP_ASYNC16(dst, src) \
    asm volatile("cp.async.cg.shared.global [%0], [%1], 16;\n" ::"r"(dst), "l"(src))
#define CP_COMMIT() asm volatile("cp.async.commit_group;\n")
#define CP_WAIT(N_) asm volatile("cp.async.wait_group %0;\n" ::"n"(N_))

// ================= fused h3 GEMM + softmax-normalize + LN + residual + relu =================
// BM=32, N=1024 in 16 tiles of 64 cols, K=128. 256 threads, fp16 h3 staging -> 2 CTAs/SM.
#define H3S2 1032                        // halves per h3 row (stride)
#define FH_A_STR 132                     // A stage stride (floats); aliased into h3 region
#define FH2_B_OFF   66048                // 32*1032*2
#define FH2_B_STR   136                  // halves per B row
#define FH2_B_SZ    17408                // 64*136*2
#define FH2_PART_OFF 100864              // FH2_B_OFF + 2*FH2_B_SZ
#define FH2_STAT_OFF 101888              // + 256 floats
#define FH2_SMEM     102144              // + 64 floats

__global__ void __launch_bounds__(256, 2)
h3_final_fused(const float* __restrict__ A, const __half* __restrict__ WbH,
               const float* __restrict__ xres, const float* __restrict__ gg,
               const float* __restrict__ bb, float* __restrict__ out) {
    extern __shared__ char sm[];
    const uint32_t sbase = smem_u32(sm);
    __half* h3h = reinterpret_cast<__half*>(sm);
    float* As   = reinterpret_cast<float*>(sm);          // aliased; dead after convert
    float* part = reinterpret_cast<float*>(sm + FH2_PART_OFF);
    float* stat = reinterpret_cast<float*>(sm + FH2_STAT_OFF);

    const int tid  = threadIdx.x;
    const int warp = tid >> 5;
    const int lane = tid & 31;
    const int wm   = warp & 1;   // 2 m-positions x 16 rows
    const int wn   = warp >> 1;  // 4 n-positions x 16 cols per tile
    const int g    = lane >> 2;
    const int t    = lane & 3;
    const int brow = blockIdx.x * 32;

    part[tid] = 0.f;

    // issue A stage (32 x 128 fp32 raw logits, into aliased region) + B tile 0
#pragma unroll
    for (int i = 0; i < 4; ++i) {
        const int linear = tid + i * 256;       // 0..1023
        const int row = linear >> 5;
        const int c   = linear & 31;
        CP_ASYNC16(sbase + row * (FH_A_STR * 4) + c * 16,
                   (const char*)A + (size_t)(brow + row) * KSLOT * 4 + c * 16);
    }
#pragma unroll
    for (int i = 0; i < 4; ++i) {
        const int linear = tid + i * 256;       // 0..1023
        const int e = linear >> 4;              // 0..63
        const int c = linear & 15;
        CP_ASYNC16(sbase + FH2_B_OFF + e * (FH2_B_STR * 2) + c * 16,
                   (const char*)WbH + (size_t)e * KSLOT * 2 + c * 16);
    }
    CP_COMMIT();
#pragma unroll
    for (int i = 0; i < 4; ++i) {
        const int linear = tid + i * 256;
        const int e = linear >> 4;
        const int c = linear & 15;
        CP_ASYNC16(sbase + FH2_B_OFF + FH2_B_SZ + e * (FH2_B_STR * 2) + c * 16,
                   (const char*)WbH + (size_t)(64 + e) * KSLOT * 2 + c * 16);
    }
    CP_COMMIT();

    uint32_t ah[8][4], al[8][4];
    float acc[2][4];
#pragma unroll
    for (int nf = 0; nf < 2; ++nf)
#pragma unroll
        for (int q = 0; q < 4; ++q) acc[nf][q] = 0.f;
    float s0 = 0.f, q0 = 0.f, s1 = 0.f, q1 = 0.f;

    for (int nt = 0; nt < 16; ++nt) {
        if (nt < 14) { CP_WAIT(1); } else { CP_WAIT(0); }
        __syncthreads();

        if (nt == 0) {
            // softmax-normalize A tile in place: p = exp(l - M)*invS, then L1 over k
            {
                const int b = brow >> 12;
                const int row = tid >> 3;
                const int c0 = (tid & 7) * 16;
                float* ar = &As[row * FH_A_STR + c0];
                float pv[16];
                float tot = 0.f;
#pragma unroll
                for (int j = 0; j < 16; ++j) {
                    const int k = c0 + j;
                    pv[j] = __expf(ar[j] - g_M[b * KSLOT + k]) * g_S[b * KSLOT + k];
                    tot += pv[j];
                }
                tot += __shfl_xor_sync(0xffffffffu, tot, 1);
                tot += __shfl_xor_sync(0xffffffffu, tot, 2);
                tot += __shfl_xor_sync(0xffffffffu, tot, 4);
                const float inv = 1.f / (1e-9f + tot);
#pragma unroll
                for (int j = 0; j < 16; ++j) ar[j] = pv[j] * inv;
            }
            __syncthreads();

            // convert this warp's A fragments once (rows wm*16+g, +8; all K)
            const int r0 = wm * 16 + g;
#pragma unroll
            for (int kk = 0; kk < 8; ++kk) {
                const int kb = kk * 16 + 2 * t;
                const float2 v0 = *reinterpret_cast<const float2*>(&As[r0 * FH_A_STR + kb]);
                const float2 v1 = *reinterpret_cast<const float2*>(&As[(r0 + 8) * FH_A_STR + kb]);
                const float2 v2 = *reinterpret_cast<const float2*>(&As[r0 * FH_A_STR + kb + 8]);
                const float2 v3 = *reinterpret_cast<const float2*>(&As[(r0 + 8) * FH_A_STR + kb + 8]);
                __half2 h;
                float2 hf;
                h = __floats2half2_rn(v0.x, v0.y); ah[kk][0] = *reinterpret_cast<uint32_t*>(&h);
                hf = __half22float2(h);
                h = __floats2half2_rn(v0.x - hf.x, v0.y - hf.y); al[kk][0] = *reinterpret_cast<uint32_t*>(&h);
                h = __floats2half2_rn(v1.x, v1.y); ah[kk][1] = *reinterpret_cast<uint32_t*>(&h);
                hf = __half22float2(h);
                h = __floats2half2_rn(v1.x - hf.x, v1.y - hf.y); al[kk][1] = *reinterpret_cast<uint32_t*>(&h);
                h = __floats2half2_rn(v2.x, v2.y); ah[kk][2] = *reinterpret_cast<uint32_t*>(&h);
                hf = __half22float2(h);
                h = __floats2half2_rn(v2.x - hf.x, v2.y - hf.y); al[kk][2] = *reinterpret_cast<uint32_t*>(&h);
                h = __floats2half2_rn(v3.x, v3.y); ah[kk][3] = *reinterpret_cast<uint32_t*>(&h);
                hf = __half22float2(h);
                h = __floats2half2_rn(v3.x - hf.x, v3.y - hf.y); al[kk][3] = *reinterpret_cast<uint32_t*>(&h);
            }
            __syncthreads();   // A region now dead; h3 writes may begin
        }

        const char* bB = sm + FH2_B_OFF + (nt & 1) * FH2_B_SZ;
#pragma unroll
        for (int kk = 0; kk < 8; ++kk) {
            uint32_t b0[2], b1[2];
#pragma unroll
            for (int nf = 0; nf < 2; ++nf) {
                const int e = wn * 16 + nf * 8 + g;
                const char* p = bB + e * (FH2_B_STR * 2) + (kk * 16 + 2 * t) * 2;
                b0[nf] = *reinterpret_cast<const uint32_t*>(p);
                b1[nf] = *reinterpret_cast<const uint32_t*>(p + 16);
            }
#pragma unroll
            for (int nf = 0; nf < 2; ++nf) {
                mma_f16(acc[nf], al[kk][0], al[kk][1], al[kk][2], al[kk][3], b0[nf], b1[nf]);
                mma_f16(acc[nf], ah[kk][0], ah[kk][1], ah[kk][2], ah[kk][3], b0[nf], b1[nf]);
            }
        }

        // store tile to h3 (fp16) + accumulate row stats, reset acc
        {
            const int r0 = wm * 16 + g;
#pragma unroll
            for (int nf = 0; nf < 2; ++nf) {
                const int col = nt * 64 + wn * 16 + nf * 8 + 2 * t;
                __half2 p0 = __floats2half2_rn(acc[nf][0], acc[nf][1]);
                __half2 p1 = __floats2half2_rn(acc[nf][2], acc[nf][3]);
                *reinterpret_cast<__half2*>(&h3h[r0 * H3S2 + col])       = p0;
                *reinterpret_cast<__half2*>(&h3h[(r0 + 8) * H3S2 + col]) = p1;
                s0 += acc[nf][0] + acc[nf][1];
                q0 += acc[nf][0] * acc[nf][0] + acc[nf][1] * acc[nf][1];
                s1 += acc[nf][2] + acc[nf][3];
                q1 += acc[nf][2] * acc[nf][2] + acc[nf][3] * acc[nf][3];
                acc[nf][0] = acc[nf][1] = acc[nf][2] = acc[nf][3] = 0.f;
            }
        }
        __syncthreads();

        if (nt + 2 < 16) {
            const int src_tile = nt + 2;
#pragma unroll
            for (int i = 0; i < 4; ++i) {
                const int linear = tid + i * 256;
                const int e = linear >> 4;
                const int c = linear & 15;
                CP_ASYNC16(sbase + FH2_B_OFF + (src_tile & 1) * FH2_B_SZ + e * (FH2_B_STR * 2) + c * 16,
                           (const char*)WbH + (size_t)(src_tile * 64 + e) * KSLOT * 2 + c * 16);
            }
            CP_COMMIT();
        }
    }

    // deterministic row-stat reduction: over t via shfl, then over 4 wn via smem
    s0 += __shfl_xor_sync(0xffffffffu, s0, 1); s0 += __shfl_xor_sync(0xffffffffu, s0, 2);
    q0 += __shfl_xor_sync(0xffffffffu, q0, 1); q0 += __shfl_xor_sync(0xffffffffu, q0, 2);
    s1 += __shfl_xor_sync(0xffffffffu, s1, 1); s1 += __shfl_xor_sync(0xffffffffu, s1, 2);
    q1 += __shfl_xor_sync(0xffffffffu, q1, 1); q1 += __shfl_xor_sync(0xffffffffu, q1, 2);
    if (t == 0) {
        const int r0 = wm * 16 + g;
        part[wn * 32 + r0]           = s0;
        part[wn * 32 + r0 + 8]       = s1;
        part[128 + wn * 32 + r0]     = q0;
        part[128 + wn * 32 + r0 + 8] = q1;
    }
    __syncthreads();

    if (tid < 32) {
        float S = 0.f, Q = 0.f;
#pragma unroll
        for (int w = 0; w < 4; ++w) {
            S += part[w * 32 + tid];
            Q += part[128 + w * 32 + tid];
        }
        const float m = S * (1.f / DD);
        stat[tid]      = m;
        stat[32 + tid] = rsqrtf(Q * (1.f / DD) - m * m + 1e-5f);
    }
    __syncthreads();

    {
        const int row  = tid >> 3;
        const int grow = brow + row;
        const float m = stat[row];
        const float r = stat[32 + row];
        const __half* h3r = &h3h[row * H3S2];
        const float* xr  = xres + (size_t)grow * DD;
        float* outr      = out + (size_t)grow * DD;
#pragma unroll 4
        for (int j = 0; j < 32; ++j) {
            const int col = (tid & 7) * 4 + j * 32;
            const __half2 ha = *reinterpret_cast<const __half2*>(&h3r[col]);
            const __half2 hb = *reinterpret_cast<const __half2*>(&h3r[col + 2]);
            const float2 f01 = __half22float2(ha);
            const float2 f23 = __half22float2(hb);
            const float4 g4 = *reinterpret_cast<const float4*>(gg + col);
            const float4 b4 = *reinterpret_cast<const float4*>(bb + col);
            const float4 xv = *reinterpret_cast<const float4*>(xr + col);
            float4 o;
            o.x = fmaxf((f01.x - m) * r * g4.x + b4.x + xv.x, 0.f);
            o.y = fmaxf((f01.y - m) * r * g4.y + b4.y + xv.y, 0.f);
            o.z = fmaxf((f23.x - m) * r * g4.z + b4.z + xv.z, 0.f);
            o.w = fmaxf((f23.y - m) * r * g4.w + b4.w + xv.w, 0.f);
            *reinterpret_cast<float4*>(outr + col) = o;
        }
    }
}

// ---------------- split-K SIMT fp32 NN GEMM (weight prep only) ----------------
__global__ void __launch_bounds__(256, 1)
prep_gemm_splitk(const float* __restrict__ A, const float* __restrict__ B,
                 float* __restrict__ P, int M, int N, int K) {
    __shared__ float As[64][17];
    __shared__ float Bs[16][64];

    const int tid = threadIdx.x;
    const int tx = tid & 15;
    const int ty = tid >> 4;
    const int bm = blockIdx.y * 64;
    const int bn = blockIdx.x * 64;
    const int kchunk = K / NSPLIT;
    const int k0 = blockIdx.z * kchunk;

    float c[4][4];
#pragma unroll
    for (int q = 0; q < 4; ++q)
#pragma unroll
        for (int r = 0; r < 4; ++r) c[q][r] = 0.f;

    const int amm = tid >> 2;
    const int akk = (tid & 3) * 4;
    const int bc  = tid & 63;
    const int br0 = tid >> 6;

    for (int kt = 0; kt < kchunk; kt += 16) {
        const float4 va = *reinterpret_cast<const float4*>(
            A + (size_t)(bm + amm) * K + k0 + kt + akk);
        As[amm][akk + 0] = va.x;
        As[amm][akk + 1] = va.y;
        As[amm][akk + 2] = va.z;
        As[amm][akk + 3] = va.w;
#pragma unroll
        for (int j = 0; j < 4; ++j) {
            const int r = br0 + j * 4;
            Bs[r][bc] = B[(size_t)(k0 + kt + r) * N + bn + bc];
        }
        __syncthreads();

#pragma unroll
        for (int kk = 0; kk < 16; ++kk) {
            const float a0 = As[ty * 4 + 0][kk];
            const float a1 = As[ty * 4 + 1][kk];
            const float a2 = As[ty * 4 + 2][kk];
            const float a3 = As[ty * 4 + 3][kk];
            const float4 b = *reinterpret_cast<const float4*>(&Bs[kk][tx * 4]);
            c[0][0] += a0 * b.x; c[0][1] += a0 * b.y; c[0][2] += a0 * b.z; c[0][3] += a0 * b.w;
            c[1][0] += a1 * b.x; c[1][1] += a1 * b.y; c[1][2] += a1 * b.z; c[1][3] += a1 * b.w;
            c[2][0] += a2 * b.x; c[2][1] += a2 * b.y; c[2][2] += a2 * b.z; c[2][3] += a2 * b.w;
            c[3][0] += a3 * b.x; c[3][1] += a3 * b.y; c[3][2] += a3 * b.z; c[3][3] += a3 * b.w;
        }
        __syncthreads();
    }

    float* Pb = P + (size_t)blockIdx.z * M * N;
#pragma unroll
    for (int q = 0; q < 4; ++q) {
        const int row = bm + ty * 4 + q;
        *reinterpret_cast<float4*>(Pb + (size_t)row * N + bn + tx * 4) =
            make_float4(c[q][0], c[q][1], c[q][2], c[q][3]);
    }
}

__global__ void reduce_partials_h(const float* __restrict__ P, __half* __restrict__ C, int total) {
    const int i = blockIdx.x * 256 + threadIdx.x;
    if (i >= total) return;
    float s = 0.f;
#pragma unroll
    for (int ss = 0; ss < NSPLIT; ++ss) s += P[(size_t)ss * total + i];
    C[i] = __float2half_rn(s);
}

// ---------------- fused LN + logits GEMM + softmax pass1 (pre-split smem, R15 WIN) ----------------
#define LG_STR 24
__global__ void __launch_bounds__(256, 2)
gemm_ln_logits(const float* __restrict__ X, const __half* __restrict__ Wah,
               const float* __restrict__ wsum, const float* __restrict__ cb,
               float* __restrict__ L) {
    __shared__ __half Ah[2][128][LG_STR];
    __shared__ __half Al[2][128][LG_STR];
    __shared__ __half Bh[2][128][LG_STR];
    __shared__ float sm_mean[128];
    __shared__ float sm_rstd[128];
    __shared__ float pm_part[4][KSLOT];
    __shared__ float ps_part[4][KSLOT];

    const int tid  = threadIdx.x;
    const int lane = tid & 31;
    const int warp = tid >> 5;
    const int wm   = warp & 3;
    const int wn   = warp >> 2;
    const int g    = lane >> 2;
    const int t    = lane & 3;

    const int brow = blockIdx.y * 128;

    float acc[2][8][4];
#pragma unroll
    for (int i = 0; i < 2; ++i)
#pragma unroll
        for (int j = 0; j < 8; ++j)
#pragma unroll
            for (int q = 0; q < 4; ++q) acc[i][j][q] = 0.f;

    const int r0 = tid >> 2;
    const int kc = (tid & 3) * 4;
    const int brB = tid >> 1;
    const int bcB = (tid & 1) * 8;

    float sumA = 0.f, sqA = 0.f, sumB = 0.f, sqB = 0.f;

    float4 pa0, pa1;
    auto ldgA = [&](int kt) {
        pa0 = *reinterpret_cast<const float4*>(X + (size_t)(brow + r0) * DD + kt * 16 + kc);
        pa1 = *reinterpret_cast<const float4*>(X + (size_t)(brow + r0 + 64) * DD + kt * 16 + kc);
    };
    auto stsA = [&](int s) {
        __half2 h0 = __floats2half2_rn(pa0.x, pa0.y);
        __half2 h1 = __floats2half2_rn(pa0.z, pa0.w);
        float2 f0 = __half22float2(h0), f1 = __half22float2(h1);
        __half2 l0 = __floats2half2_rn(pa0.x - f0.x, pa0.y - f0.y);
        __half2 l1 = __floats2half2_rn(pa0.z - f1.x, pa0.w - f1.y);
        *reinterpret_cast<__half2*>(&Ah[s][r0][kc])     = h0;
        *reinterpret_cast<__half2*>(&Ah[s][r0][kc + 2]) = h1;
        *reinterpret_cast<__half2*>(&Al[s][r0][kc])     = l0;
        *reinterpret_cast<__half2*>(&Al[s][r0][kc + 2]) = l1;
        sumA += pa0.x + pa0.y + pa0.z + pa0.w;
        sqA  += pa0.x * pa0.x + pa0.y * pa0.y + pa0.z * pa0.z + pa0.w * pa0.w;
        __half2 h2 = __floats2half2_rn(pa1.x, pa1.y);
        __half2 h3 = __floats2half2_rn(pa1.z, pa1.w);
        float2 f2 = __half22float2(h2), f3 = __half22float2(h3);
        __half2 l2 = __floats2half2_rn(pa1.x - f2.x, pa1.y - f2.y);
        __half2 l3 = __floats2half2_rn(pa1.z - f3.x, pa1.w - f3.y);
        *reinterpret_cast<__half2*>(&Ah[s][r0 + 64][kc])     = h2;
        *reinterpret_cast<__half2*>(&Ah[s][r0 + 64][kc + 2]) = h3;
        *reinterpret_cast<__half2*>(&Al[s][r0 + 64][kc])     = l2;
        *reinterpret_cast<__half2*>(&Al[s][r0 + 64][kc + 2]) = l3;
        sumB += pa1.x + pa1.y + pa1.z + pa1.w;
        sqB  += pa1.x * pa1.x + pa1.y * pa1.y + pa1.z * pa1.z + pa1.w * pa1.w;
    };
    auto issueB = [&](int kt, int s) {
        CP_ASYNC16(smem_u32(&Bh[s][brB][bcB]),
                   Wah + (size_t)brB * DD + kt * 16 + bcB);
    };

    ldgA(0);
    issueB(0, 0);
    CP_COMMIT();

    for (int kt = 0; kt < DD / 16; ++kt) {
        const int cur = kt & 1;
        const bool more = (kt + 1 < DD / 16);
        if (more) {
            issueB(kt + 1, cur ^ 1);
            CP_COMMIT();
        }
        stsA(cur);
        if (more) ldgA(kt + 1);
        if (more) { CP_WAIT(1); } else { CP_WAIT(0); }
        __syncthreads();

        uint32_t ah[2][4], al[2][4];
#pragma unroll
        for (int mt = 0; mt < 2; ++mt) {
            const int row = wm * 32 + mt * 16 + g;
            ah[mt][0] = *reinterpret_cast<const uint32_t*>(&Ah[cur][row][2 * t]);
            ah[mt][1] = *reinterpret_cast<const uint32_t*>(&Ah[cur][row + 8][2 * t]);
            ah[mt][2] = *reinterpret_cast<const uint32_t*>(&Ah[cur][row][2 * t + 8]);
            ah[mt][3] = *reinterpret_cast<const uint32_t*>(&Ah[cur][row + 8][2 * t + 8]);
            al[mt][0] = *reinterpret_cast<const uint32_t*>(&Al[cur][row][2 * t]);
            al[mt][1] = *reinterpret_cast<const uint32_t*>(&Al[cur][row + 8][2 * t]);
            al[mt][2] = *reinterpret_cast<const uint32_t*>(&Al[cur][row][2 * t + 8]);
            al[mt][3] = *reinterpret_cast<const uint32_t*>(&Al[cur][row + 8][2 * t + 8]);
        }

        uint32_t bh[8][2];
#pragma unroll
        for (int nt = 0; nt < 8; ++nt) {
            const int col = wn * 64 + nt * 8 + g;
            bh[nt][0] = *reinterpret_cast<const uint32_t*>(&Bh[cur][col][2 * t]);
            bh[nt][1] = *reinterpret_cast<const uint32_t*>(&Bh[cur][col][2 * t + 8]);
        }

#pragma unroll
        for (int mt = 0; mt < 2; ++mt)
#pragma unroll
            for (int nt = 0; nt < 8; ++nt) {
                mma_f16(acc[mt][nt], al[mt][0], al[mt][1], al[mt][2], al[mt][3],
                        bh[nt][0], bh[nt][1]);
                mma_f16(acc[mt][nt], ah[mt][0], ah[mt][1], ah[mt][2], ah[mt][3],
                        bh[nt][0], bh[nt][1]);
            }
        __syncthreads();
    }

#pragma unroll
    for (int o = 1; o <= 2; o <<= 1) {
        sumA += __shfl_xor_sync(0xffffffffu, sumA, o);
        sqA  += __shfl_xor_sync(0xffffffffu, sqA, o);
        sumB += __shfl_xor_sync(0xffffffffu, sumB, o);
        sqB  += __shfl_xor_sync(0xffffffffu, sqB, o);
    }
    if ((tid & 3) == 0) {
        const float mA = sumA * (1.f / DD);
        const float mB = sumB * (1.f / DD);
        sm_mean[r0]      = mA;
        sm_mean[r0 + 64] = mB;
        sm_rstd[r0]      = rsqrtf(sqA * (1.f / DD) - mA * mA + 1e-5f);
        sm_rstd[r0 + 64] = rsqrtf(sqB * (1.f / DD) - mB * mB + 1e-5f);
    }
    __syncthreads();

#pragma unroll
    for (int mt = 0; mt < 2; ++mt) {
        const int lrow0 = wm * 32 + mt * 16 + g;
        const float m0 = sm_mean[lrow0],     r0s = sm_rstd[lrow0];
        const float m1 = sm_mean[lrow0 + 8], r1s = sm_rstd[lrow0 + 8];
        const int row = brow + lrow0;
#pragma unroll
        for (int nt = 0; nt < 8; ++nt) {
            const int col = wn * 64 + nt * 8 + t * 2;
            const float ws0 = wsum[col], ws1 = wsum[col + 1];
            const float cb0 = cb[col],   cb1 = cb[col + 1];
            acc[mt][nt][0] = r0s * (acc[mt][nt][0] - m0 * ws0) + cb0;
            acc[mt][nt][1] = r0s * (acc[mt][nt][1] - m0 * ws1) + cb1;
            acc[mt][nt][2] = r1s * (acc[mt][nt][2] - m1 * ws0) + cb0;
            acc[mt][nt][3] = r1s * (acc[mt][nt][3] - m1 * ws1) + cb1;
            *reinterpret_cast<float2*>(L + (size_t)row * KSLOT + col) =
                make_float2(acc[mt][nt][0], acc[mt][nt][1]);
            *reinterpret_cast<float2*>(L + (size_t)(row + 8) * KSLOT + col) =
                make_float2(acc[mt][nt][2], acc[mt][nt][3]);
        }
    }

#pragma unroll
    for (int nt = 0; nt < 8; ++nt) {
        float m0 = fmaxf(fmaxf(acc[0][nt][0], acc[0][nt][2]), fmaxf(acc[1][nt][0], acc[1][nt][2]));
        float m1 = fmaxf(fmaxf(acc[0][nt][1], acc[0][nt][3]), fmaxf(acc[1][nt][1], acc[1][nt][3]));
#pragma unroll
        for (int o = 4; o <= 16; o <<= 1) {
            m0 = fmaxf(m0, __shfl_xor_sync(0xffffffffu, m0, o));
            m1 = fmaxf(m1, __shfl_xor_sync(0xffffffffu, m1, o));
        }
        float sc0 = __expf(acc[0][nt][0] - m0) + __expf(acc[0][nt][2] - m0) +
                    __expf(acc[1][nt][0] - m0) + __expf(acc[1][nt][2] - m0);
        float sc1 = __expf(acc[0][nt][1] - m1) + __expf(acc[0][nt][3] - m1) +
                    __expf(acc[1][nt][1] - m1) + __expf(acc[1][nt][3] - m1);
#pragma unroll
        for (int o = 4; o <= 16; o <<= 1) {
            sc0 += __shfl_xor_sync(0xffffffffu, sc0, o);
            sc1 += __shfl_xor_sync(0xffffffffu, sc1, o);
        }
        if (lane < 4) {
            const int col = wn * 64 + nt * 8 + 2 * t;
            pm_part[wm][col]     = m0;
            ps_part[wm][col]     = sc0;
            pm_part[wm][col + 1] = m1;
            ps_part[wm][col + 1] = sc1;
        }
    }
    __syncthreads();

    if (tid < KSLOT) {
        float M = fmaxf(fmaxf(pm_part[0][tid], pm_part[1][tid]),
                        fmaxf(pm_part[2][tid], pm_part[3][tid]));
        float S = ps_part[0][tid] * __expf(pm_part[0][tid] - M) +
                  ps_part[1][tid] * __expf(pm_part[1][tid] - M) +
                  ps_part[2][tid] * __expf(pm_part[2][tid] - M) +
                  ps_part[3][tid] * __expf(pm_part[3][tid] - M);
        g_pm[blockIdx.y * KSLOT + tid] = M;
        g_ps[blockIdx.y * KSLOT + tid] = S;
    }
}

// ---------------- prep: reduce Wa partials + build Wah/wsum/cb (ba folded in) ----------------
__global__ void prep_wag_kernel(const float* __restrict__ Pa, const float* __restrict__ gg,
                                const float* __restrict__ bb, const float* __restrict__ w0,
                                const float* __restrict__ b_in,
                                __half* __restrict__ Wah, float* __restrict__ wsum,
                                float* __restrict__ cb) {
    const int k = blockIdx.x;
    const int tid = threadIdx.x;  // 256
    float4 w = make_float4(0.f, 0.f, 0.f, 0.f);
#pragma unroll
    for (int ss = 0; ss < NSPLIT; ++ss) {
        const float4 p = reinterpret_cast<const float4*>(
            Pa + (size_t)ss * KSLOT * DD + (size_t)k * DD)[tid];
        w.x += p.x; w.y += p.y; w.z += p.z; w.w += p.w;
    }
    const float4 g4 = reinterpret_cast<const float4*>(gg)[tid];
    const float4 b4 = reinterpret_cast<const float4*>(bb)[tid];
    float4 wg;
    wg.x = w.x * g4.x; wg.y = w.y * g4.y; wg.z = w.z * g4.z; wg.w = w.w * g4.w;
    __half2 wh0 = __floats2half2_rn(wg.x, wg.y);
    __half2 wh1 = __floats2half2_rn(wg.z, wg.w);
    *reinterpret_cast<__half2*>(Wah + (size_t)k * DD + 4 * tid)     = wh0;
    *reinterpret_cast<__half2*>(Wah + (size_t)k * DD + 4 * tid + 2) = wh1;

    const float4 w0v = reinterpret_cast<const float4*>(w0 + (size_t)k * DD)[tid];
    const float4 biv = reinterpret_cast<const float4*>(b_in)[tid];

    float s = wg.x + wg.y + wg.z + wg.w;
    float c = w.x * b4.x + w.y * b4.y + w.z * b4.z + w.w * b4.w
            + w0v.x * biv.x + w0v.y * biv.y + w0v.z * biv.z + w0v.w * biv.w;
#pragma unroll
    for (int o = 16; o > 0; o >>= 1) {
        s += __shfl_xor_sync(0xffffffffu, s, o);
        c += __shfl_xor_sync(0xffffffffu, c, o);
    }
    __shared__ float rs[8], rc[8];
    if ((tid & 31) == 0) { rs[tid >> 5] = s; rc[tid >> 5] = c; }
    __syncthreads();
    if (tid == 0) {
        float S = 0.f, C = 0.f;
#pragma unroll
        for (int i = 0; i < 8; ++i) { S += rs[i]; C += rc[i]; }
        wsum[k] = S;
        cb[k] = C;
    }
}

// ---------------- softmax pass2: combine chunk partials (stores 1/S) ----------------
__global__ void softmax_pass2() {
    const int b = blockIdx.x;
    const int k = threadIdx.x;  // 128
    float M = NEG_INF;
#pragma unroll
    for (int c = 0; c < NCHUNK; ++c) M = fmaxf(M, g_pm[(b * NCHUNK + c) * KSLOT + k]);
    float S = 0.f;
#pragma unroll
    for (int c = 0; c < NCHUNK; ++c)
        S += g_ps[(b * NCHUNK + c) * KSLOT + k] * __expf(g_pm[(b * NCHUNK + c) * KSLOT + k] - M);
    g_M[b * KSLOT + k] = M;
    g_S[b * KSLOT + k] = 1.f / S;
}

// ---------------- launch ----------------
extern "C" void kernel_launch(void* const* d_in, const int* in_sizes, int n_in,
                              void* d_out, int out_size) {
    const float* x     = (const float*)d_in[0];
    const float* ln_g  = (const float*)d_in[1];
    const float* ln_b  = (const float*)d_in[2];
    const float* w_in  = (const float*)d_in[3];
    const float* b_in  = (const float*)d_in[4];
    const float* w0    = (const float*)d_in[5];
    const float* w1    = (const float*)d_in[6];
    const float* w_out = (const float*)d_in[7];
    const float* og    = (const float*)d_in[8];
    const float* ob    = (const float*)d_in[9];
    float* out = (float*)d_out;

    static float* logits = nullptr;
    static float* Pa = nullptr; static float* Pb = nullptr;
    static float* wsum = nullptr; static float* cb = nullptr;
    static __half* Wah = nullptr; static __half* WbH = nullptr;
    static cudaStream_t s2 = nullptr;
    static cudaEvent_t evF = nullptr, evJ = nullptr;
    if (!logits) {
        cudaGetSymbolAddress((void**)&logits, g_logits);
        cudaGetSymbolAddress((void**)&Pa, g_Pa);
        cudaGetSymbolAddress((void**)&Pb, g_Pb);
        cudaGetSymbolAddress((void**)&wsum, g_wsum);
        cudaGetSymbolAddress((void**)&cb, g_cb);
        cudaGetSymbolAddress((void**)&Wah, g_Wah);
        cudaGetSymbolAddress((void**)&WbH, g_WbH);
        cudaFuncSetAttribute(h3_final_fused, cudaFuncAttributeMaxDynamicSharedMemorySize, FH2_SMEM);
        cudaStreamCreateWithFlags(&s2, cudaStreamNonBlocking);
        cudaEventCreateWithFlags(&evF, cudaEventDisableTiming);
        cudaEventCreateWithFlags(&evJ, cudaEventDisableTiming);
    }

    // ---- fork: WbH prep chain on s2 ----
    cudaEventRecord(evF, 0);
    cudaStreamWaitEvent(s2, evF, 0);
    prep_gemm_splitk<<<dim3(KSLOT / 64, DD / 64, NSPLIT), 256, 0, s2>>>(w_out, w1, Pb, DD, KSLOT, DD);
    reduce_partials_h<<<(DD * KSLOT + 255) / 256, 256, 0, s2>>>(Pb, WbH, DD * KSLOT);
    cudaEventRecord(evJ, s2);

    // ---- main stream: Wa chain + logits path ----
    prep_gemm_splitk<<<dim3(DD / 64, KSLOT / 64, NSPLIT), 256>>>(w0, w_in, Pa, KSLOT, DD, DD);
    prep_wag_kernel<<<KSLOT, 256>>>(Pa, ln_g, ln_b, w0, b_in, Wah, wsum, cb);

    gemm_ln_logits<<<dim3(1, MTOT / 128), 256>>>(x, Wah, wsum, cb, logits);
    softmax_pass2<<<BB, 128>>>();

    // ---- join, then fused h3 ----
    cudaStreamWaitEvent(0, evJ, 0);
    h3_final_fused<<<MTOT / 32, 256, FH2_SMEM>>>(logits, WbH, x, og, ob, out);
}